// round 11
// baseline (speedup 1.0000x reference)
#include <cuda_runtime.h>
#include <cuda_fp16.h>
#include <cuda_bf16.h>
#include <cstdint>

#define NN 40000
#define EE 640000
#define DD 128
#define LL 5
#define NTILES 625          // NN / 64 (64-row GEMM tiles, exact)

// ---------------- device scratch (static, no allocation) ----------------
__device__ float g_z0[NN * DD];   // gemm2 output
__device__ float g_y1[NN * DD];   // gemm1 output
__device__ __half g_hh[NN * DD];  // fp16 shadow of h (gather source)
__device__ int   g_rowptr[NN + 1];
__device__ int   g_cursor[NN];
__device__ int   g_packed[EE];    // (src<<5) | (attr*32)<<21, grouped by dst
__device__ int   g_bflag[40];
__device__ int   g_bpre[40];
__device__ int   g_bar;
__device__ int   g_ctr[10];       // per-layer work-stealing counters (2 per layer)
__device__ float g_s1[LL * DD], g_q1[LL * DD];   // gemm1 output stats (BN1), per layer
__device__ float g_s2[LL * DD], g_q2[LL * DD];   // gemm2 output stats (BN2), per layer
__device__ uint4 g_wth4[10 * 2048];
__device__ uint4 g_wtl4[10 * 2048];

// ---------------- helpers ----------------
__device__ __forceinline__ uint32_t smem_u32(const void* p) {
    uint32_t a;
    asm("{ .reg .u64 t; cvta.to.shared.u64 t, %1; cvt.u32.u64 %0, t; }" : "=r"(a) : "l"(p));
    return a;
}
__device__ __forceinline__ void ldsm4(uint32_t a, uint32_t& r0, uint32_t& r1,
                                      uint32_t& r2, uint32_t& r3) {
    asm volatile("ldmatrix.sync.aligned.m8n8.x4.shared.b16 {%0,%1,%2,%3}, [%4];"
                 : "=r"(r0), "=r"(r1), "=r"(r2), "=r"(r3) : "r"(a));
}
__device__ __forceinline__ void mma16816(float* c, const uint32_t* a, uint32_t b0, uint32_t b1) {
    asm volatile(
        "mma.sync.aligned.m16n8k16.row.col.f32.bf16.bf16.f32 "
        "{%0,%1,%2,%3}, {%4,%5,%6,%7}, {%8,%9}, {%0,%1,%2,%3};"
        : "+f"(c[0]), "+f"(c[1]), "+f"(c[2]), "+f"(c[3])
        : "r"(a[0]), "r"(a[1]), "r"(a[2]), "r"(a[3]), "r"(b0), "r"(b1));
}
__device__ __forceinline__ void split2(float a, float b, uint32_t& hi, uint32_t& lo) {
    __nv_bfloat16 ha = __float2bfloat16_rn(a), hb = __float2bfloat16_rn(b);
    float ra = a - __bfloat162float(ha), rb = b - __bfloat162float(hb);
    __nv_bfloat162 ph = __halves2bfloat162(ha, hb);
    __nv_bfloat162 pl = __halves2bfloat162(__float2bfloat16_rn(ra), __float2bfloat16_rn(rb));
    hi = *(uint32_t*)&ph;
    lo = *(uint32_t*)&pl;
}
__device__ __forceinline__ uint2 f2h4(float4 v) {
    __half2 lo = __floats2half2_rn(v.x, v.y);
    __half2 hi = __floats2half2_rn(v.z, v.w);
    uint2 r;
    r.x = *(unsigned*)&lo;
    r.y = *(unsigned*)&hi;
    return r;
}
__device__ __forceinline__ void msg2(uint2 r, uint2 e, __half2& m0, __half2& m1, __half2 z2) {
    m0 = __hmax2(__hadd2(*(__half2*)&r.x, *(__half2*)&e.x), z2);
    m1 = __hmax2(__hadd2(*(__half2*)&r.y, *(__half2*)&e.y), z2);
}

// ---------------- embed + wconv + per-replay zeroing + fp16 shadow ----------------
__global__ void embed_kernel(float4* __restrict__ h4,
                             const int* __restrict__ x_ids,
                             const float4* __restrict__ atom4,
                             const float* __restrict__ W1,
                             const float* __restrict__ W2) {
    int blk = blockIdx.x;
    if (blk < 5000) {
        int i = blk * 256 + threadIdx.x;
        if (i < NN) g_cursor[i] = 0;
        if (i < 40) { g_bflag[i] = 0; g_bpre[i] = 0; }
        if (i < 10) g_ctr[i] = 0;
        if (i == 42) g_bar = 0;
        if (i < LL * DD) { g_s1[i] = 0.f; g_q1[i] = 0.f; g_s2[i] = 0.f; g_q2[i] = 0.f; }
        int n = i >> 5, c = i & 31;
        float4 v = __ldg(&atom4[x_ids[n] * 32 + c]);
        h4[i] = v;
        ((uint2*)g_hh)[i] = f2h4(v);
    } else {
        int i = (blk - 5000) * 256 + threadIdx.x;   // 0..163839
        int which = i >> 14;
        int j = i & 16383;
        int n = j >> 7, k = j & 127;
        const float* W = ((which & 1) ? W2 : W1) + (which >> 1) * DD * DD;
        float v = __ldg(&W[k * DD + n]);
        __nv_bfloat16 h = __float2bfloat16_rn(v);
        float r = v - __bfloat162float(h);
        ((__nv_bfloat16*)g_wth4)[i] = h;
        ((__nv_bfloat16*)g_wtl4)[i] = __float2bfloat16_rn(r);
    }
}

// ---------------- CSR build ----------------
__global__ void hist_kernel(const int* __restrict__ ei) {
    int e = blockIdx.x * 256 + threadIdx.x;
    atomicAdd(&g_cursor[ei[EE + e]], 1);
}

__global__ void __launch_bounds__(1024) scan_scatter_kernel(const int* __restrict__ ei,
                                                            const int* __restrict__ eattr) {
    __shared__ int wsum[32];
    __shared__ int s_boff;
    int tid = threadIdx.x, lane = tid & 31, wid = tid >> 5;
    int b = blockIdx.x;
    int i = b * 1024 + tid;
    int v = (i < NN) ? g_cursor[i] : 0;
    int x = v;
    #pragma unroll
    for (int o = 1; o < 32; o <<= 1) { int t = __shfl_up_sync(~0u, x, o); if (lane >= o) x += t; }
    if (lane == 31) wsum[wid] = x;
    __syncthreads();
    if (wid == 0) {
        int y = wsum[lane];
        #pragma unroll
        for (int o = 1; o < 32; o <<= 1) { int t = __shfl_up_sync(~0u, y, o); if (lane >= o) y += t; }
        wsum[lane] = y;
    }
    __syncthreads();
    int incl = (wid ? wsum[wid - 1] : 0) + x;
    if (tid == 0) {
        int total = wsum[31];
        int p = 0;
        if (b > 0) {
            while (((volatile int*)g_bflag)[b - 1] == 0) { }
            p = ((volatile int*)g_bpre)[b - 1];
        }
        g_bpre[b] = p + total;
        __threadfence();
        ((volatile int*)g_bflag)[b] = 1;
        s_boff = p;
    }
    __syncthreads();
    int boff = s_boff;
    if (i < NN) {
        g_rowptr[i + 1] = boff + incl;
        g_cursor[i] = boff + incl - v;
    }
    if (i == 0) g_rowptr[0] = 0;
    __threadfence();
    __syncthreads();
    if (tid == 0) atomicAdd(&g_bar, 1);
    if (tid == 0) { while (((volatile int*)&g_bar)[0] < 40) { } }
    __syncthreads();
    for (int e = b * 16000 + tid; e < (b + 1) * 16000; e += 1024) {
        int d = ei[EE + e];
        int p = atomicAdd(&g_cursor[d], 1);
        g_packed[p] = (ei[e] << 5) | ((eattr[e] << 5) << 21);
    }
}

// ---------------- smem layout (shared by fused + gemm2) ----------------
#define SM_AH    0
#define SM_AL    17408
#define SM_BH    34816
#define SM_BL    69632
#define SM_SUM   104448
#define SM_SQ    104960
#define SM_SCALE 105472
#define SM_SHIFT 105984
#define SM_TILE  106496
#define SM_BOND  106512
#define SMEM_GEMM  106512
#define SMEM_FUSED 107536

// ---------------- FUSED agg + gemm1 (persistent, work-stealing) ----------------
// per tile: aggregate 64 rows (half2 gather) straight into A smem (bf16 split),
// then C = A @ W1 + b1 with fused column stats into g_s1/g_q1[l].
__global__ void __launch_bounds__(256, 2) agg_gemm1_kernel(const float4* __restrict__ h4,
                                                           const float* __restrict__ bond_emb,
                                                           const float* __restrict__ eps_p,
                                                           int l,
                                                           const float* __restrict__ bias) {
    extern __shared__ char smem[];
    uint32_t sb = smem_u32(smem);
    float* s_sum = (float*)(smem + SM_SUM);
    float* s_sq  = (float*)(smem + SM_SQ);
    int*   s_tile = (int*)(smem + SM_TILE);
    uint2* sbe2  = (uint2*)(smem + SM_BOND);
    float* C = g_y1;

    int tid = threadIdx.x, lane = tid & 31, wid = tid >> 5;
    if (tid < 128) {
        s_sum[tid] = 0.f; s_sq[tid] = 0.f;
        sbe2[tid] = f2h4(__ldg((const float4*)(bond_emb + l * 512) + tid));
    }
    {   // stage B = W1[l] (hi/lo bf16) once per CTA
        const uint4* srcH = g_wth4 + (l * 2) * 2048;
        const uint4* srcL = g_wtl4 + (l * 2) * 2048;
        #pragma unroll
        for (int it = 0; it < 8; it++) {
            int s = it * 256 + tid;
            int row = s >> 4, ch = s & 15;
            *(uint4*)(smem + SM_BH + row * 272 + ch * 16) = __ldg(&srcH[row * 16 + ch]);
            *(uint4*)(smem + SM_BL + row * 272 + ch * 16) = __ldg(&srcL[row * 16 + ch]);
        }
    }
    float ep = 1.0f + __ldg(&eps_p[l]);
    const uint2* hh2 = (const uint2*)g_hh;
    const __half2 z2 = __float2half2_rn(0.f);

    int mrow = (wid & 1) * 32;
    int ncol = (wid >> 1) * 32;
    int gm = lane & 7, gh = (lane >> 3) & 1, gk = lane >> 4;
    uint32_t aA0 = sb + (mrow + gm + gh * 8) * 272 + gk * 16;
    uint32_t aB0 = sb + (ncol + gm + gh * 8) * 272 + gk * 16;
    __syncthreads();   // bond emb visible before agg phase

    for (;;) {
        if (tid == 0) *s_tile = atomicAdd(&g_ctr[l * 2], 1);
        __syncthreads();
        int t = *s_tile;
        if (t >= NTILES) break;
        int rowblk = t * 64;

        // ---- agg phase: 8 warps x 8 nodes -> A smem (bf16 hi/lo) ----
        #pragma unroll 1
        for (int i = 0; i < 8; i++) {
            int row = wid * 8 + i;
            int v = rowblk + row;
            float4 hv = __ldg(&h4[v * 32 + lane]);
            float4 acc = make_float4(hv.x * ep, hv.y * ep, hv.z * ep, hv.w * ep);
            int start = g_rowptr[v], end = g_rowptr[v + 1];
            for (int base = start; base < end; base += 32) {
                int nl = min(32, end - base);
                int pk = (base + lane < end) ? g_packed[base + lane] : 0;
                int j = 0;
                for (; j + 4 <= nl; j += 4) {
                    int p0 = __shfl_sync(~0u, pk, j);
                    int p1 = __shfl_sync(~0u, pk, j + 1);
                    int p2 = __shfl_sync(~0u, pk, j + 2);
                    int p3 = __shfl_sync(~0u, pk, j + 3);
                    uint2 r0 = __ldg(&hh2[(p0 & 0x1FFFFF) + lane]);
                    uint2 r1 = __ldg(&hh2[(p1 & 0x1FFFFF) + lane]);
                    uint2 r2 = __ldg(&hh2[(p2 & 0x1FFFFF) + lane]);
                    uint2 r3 = __ldg(&hh2[(p3 & 0x1FFFFF) + lane]);
                    uint2 e0 = sbe2[((unsigned)p0 >> 21) + lane];
                    uint2 e1 = sbe2[((unsigned)p1 >> 21) + lane];
                    uint2 e2 = sbe2[((unsigned)p2 >> 21) + lane];
                    uint2 e3 = sbe2[((unsigned)p3 >> 21) + lane];
                    __half2 a0, a1, b0, b1, m0, m1;
                    msg2(r0, e0, a0, a1, z2);
                    msg2(r1, e1, b0, b1, z2);
                    msg2(r2, e2, m0, m1, z2);
                    a0 = __hadd2(a0, m0); a1 = __hadd2(a1, m1);
                    msg2(r3, e3, m0, m1, z2);
                    b0 = __hadd2(b0, m0); b1 = __hadd2(b1, m1);
                    float2 fa0 = __half22float2(a0), fa1 = __half22float2(a1);
                    float2 fb0 = __half22float2(b0), fb1 = __half22float2(b1);
                    acc.x += fa0.x + fb0.x;
                    acc.y += fa0.y + fb0.y;
                    acc.z += fa1.x + fb1.x;
                    acc.w += fa1.y + fb1.y;
                }
                for (; j < nl; j++) {
                    int p0 = __shfl_sync(~0u, pk, j);
                    uint2 r0 = __ldg(&hh2[(p0 & 0x1FFFFF) + lane]);
                    uint2 e0 = sbe2[((unsigned)p0 >> 21) + lane];
                    __half2 m0, m1;
                    msg2(r0, e0, m0, m1, z2);
                    float2 f0 = __half22float2(m0), f1 = __half22float2(m1);
                    acc.x += f0.x; acc.y += f0.y; acc.z += f1.x; acc.w += f1.y;
                }
            }
            uint32_t h0, l0, h1, l1;
            split2(acc.x, acc.y, h0, l0);
            split2(acc.z, acc.w, h1, l1);
            char* p = smem + row * 272 + lane * 8;
            *(uint2*)(p + SM_AH) = make_uint2(h0, h1);
            *(uint2*)(p + SM_AL) = make_uint2(l0, l1);
        }
        __syncthreads();

        // ---- MMA phase ----
        float c[2][4][4];
        #pragma unroll
        for (int mb = 0; mb < 2; mb++)
            #pragma unroll
            for (int i = 0; i < 4; i++)
                #pragma unroll
                for (int j = 0; j < 4; j++) c[mb][i][j] = 0.f;

        #pragma unroll
        for (int ks = 0; ks < 8; ks++) {
            uint32_t off = ks * 32;
            uint32_t ah[8], al[8], bh[8], bl[8];
            ldsm4(aA0 + SM_AH + off,            ah[0], ah[1], ah[2], ah[3]);
            ldsm4(aA0 + SM_AH + 16 * 272 + off, ah[4], ah[5], ah[6], ah[7]);
            ldsm4(aA0 + SM_AL + off,            al[0], al[1], al[2], al[3]);
            ldsm4(aA0 + SM_AL + 16 * 272 + off, al[4], al[5], al[6], al[7]);
            ldsm4(aB0 + SM_BH + off,            bh[0], bh[1], bh[2], bh[3]);
            ldsm4(aB0 + SM_BH + 16 * 272 + off, bh[4], bh[5], bh[6], bh[7]);
            ldsm4(aB0 + SM_BL + off,            bl[0], bl[1], bl[2], bl[3]);
            ldsm4(aB0 + SM_BL + 16 * 272 + off, bl[4], bl[5], bl[6], bl[7]);
            #pragma unroll
            for (int mb = 0; mb < 2; mb++) {
                #pragma unroll
                for (int ng = 0; ng < 4; ng++) {
                    int bi = (ng >> 1) * 4 + (ng & 1);
                    mma16816(c[mb][ng], ah + mb * 4, bh[bi], bh[bi + 2]);
                    mma16816(c[mb][ng], al + mb * 4, bh[bi], bh[bi + 2]);
                    mma16816(c[mb][ng], ah + mb * 4, bl[bi], bl[bi + 2]);
                }
            }
        }

        // ---- epilogue: bias, store y1, column stats ----
        #pragma unroll
        for (int ng = 0; ng < 4; ng++) {
            int col0 = ncol + ng * 8 + 2 * (lane & 3);
            float bx = __ldg(&bias[col0]), by = __ldg(&bias[col0 + 1]);
            float sx0 = 0.f, sq0 = 0.f, sx1 = 0.f, sq1 = 0.f;
            #pragma unroll
            for (int mb = 0; mb < 2; mb++) {
                int r0g = rowblk + mrow + mb * 16 + (lane >> 2);
                float x0 = c[mb][ng][0] + bx, x1 = c[mb][ng][1] + by;
                float x2 = c[mb][ng][2] + bx, x3 = c[mb][ng][3] + by;
                *(float2*)(C + r0g * DD + col0)       = make_float2(x0, x1);
                *(float2*)(C + (r0g + 8) * DD + col0) = make_float2(x2, x3);
                sx0 += x0 + x2; sq0 += x0 * x0 + x2 * x2;
                sx1 += x1 + x3; sq1 += x1 * x1 + x3 * x3;
            }
            #pragma unroll
            for (int d = 4; d < 32; d <<= 1) {
                sx0 += __shfl_xor_sync(~0u, sx0, d);
                sq0 += __shfl_xor_sync(~0u, sq0, d);
                sx1 += __shfl_xor_sync(~0u, sx1, d);
                sq1 += __shfl_xor_sync(~0u, sq1, d);
            }
            if ((lane >> 2) == 0) {
                atomicAdd(&s_sum[col0], sx0);
                atomicAdd(&s_sum[col0 + 1], sx1);
                atomicAdd(&s_sq[col0], sq0);
                atomicAdd(&s_sq[col0 + 1], sq1);
            }
        }
        __syncthreads();
    }
    __syncthreads();
    if (tid < 128) {
        atomicAdd(&g_s1[l * DD + tid], s_sum[tid]);
        atomicAdd(&g_q1[l * DD + tid], s_sq[tid]);
    }
}

// ---------------- gemm2: C = relu(BN1(y1)) @ W2 + b2, stats into g_s2/g_q2 ----------------
__global__ void __launch_bounds__(256, 2) gemm2_kernel(int l,
                                                       const float* __restrict__ bias,
                                                       const float* __restrict__ gamma,
                                                       const float* __restrict__ beta) {
    extern __shared__ char smem[];
    uint32_t sb = smem_u32(smem);
    float* s_sum   = (float*)(smem + SM_SUM);
    float* s_sq    = (float*)(smem + SM_SQ);
    float* s_scale = (float*)(smem + SM_SCALE);
    float* s_shift = (float*)(smem + SM_SHIFT);
    int*   s_tile  = (int*)(smem + SM_TILE);
    const float* A = g_y1;
    float* C = g_z0;

    int tid = threadIdx.x, lane = tid & 31, wid = tid >> 5;
    if (tid < 128) {
        s_sum[tid] = 0.f; s_sq[tid] = 0.f;
        const float invN = 1.0f / (float)NN;
        float m   = g_s1[l * DD + tid] * invN;
        float var = g_q1[l * DD + tid] * invN - m * m;
        float sc  = __ldg(&gamma[tid]) * rsqrtf(var + 1e-5f);
        s_scale[tid] = sc;
        s_shift[tid] = __ldg(&beta[tid]) - m * sc;
    }
    {   // stage B = W2[l]
        const uint4* srcH = g_wth4 + (l * 2 + 1) * 2048;
        const uint4* srcL = g_wtl4 + (l * 2 + 1) * 2048;
        #pragma unroll
        for (int it = 0; it < 8; it++) {
            int s = it * 256 + tid;
            int row = s >> 4, ch = s & 15;
            *(uint4*)(smem + SM_BH + row * 272 + ch * 16) = __ldg(&srcH[row * 16 + ch]);
            *(uint4*)(smem + SM_BL + row * 272 + ch * 16) = __ldg(&srcL[row * 16 + ch]);
        }
    }

    int mrow = (wid & 1) * 32;
    int ncol = (wid >> 1) * 32;
    int gm = lane & 7, gh = (lane >> 3) & 1, gk = lane >> 4;
    uint32_t aA0 = sb + (mrow + gm + gh * 8) * 272 + gk * 16;
    uint32_t aB0 = sb + (ncol + gm + gh * 8) * 272 + gk * 16;
    int ar = tid >> 5, ac4 = tid & 31;
    __syncthreads();   // scale/shift ready

    for (;;) {
        if (tid == 0) *s_tile = atomicAdd(&g_ctr[l * 2 + 1], 1);
        __syncthreads();
        int t = *s_tile;
        if (t >= NTILES) break;
        int rowblk = t * 64;

        {   // stage A tile with BN1+relu + bf16 split
            float4 sc = *(const float4*)(s_scale + ac4 * 4);
            float4 sh = *(const float4*)(s_shift + ac4 * 4);
            #pragma unroll
            for (int i = 0; i < 8; i++) {
                int rr = ar + i * 8;
                float4 v = __ldg((const float4*)(A + (rowblk + rr) * DD) + ac4);
                v.x = fmaxf(fmaf(v.x, sc.x, sh.x), 0.f);
                v.y = fmaxf(fmaf(v.y, sc.y, sh.y), 0.f);
                v.z = fmaxf(fmaf(v.z, sc.z, sh.z), 0.f);
                v.w = fmaxf(fmaf(v.w, sc.w, sh.w), 0.f);
                uint32_t h0, l0, h1, l1;
                split2(v.x, v.y, h0, l0);
                split2(v.z, v.w, h1, l1);
                char* p = smem + rr * 272 + ac4 * 8;
                *(uint2*)(p + SM_AH) = make_uint2(h0, h1);
                *(uint2*)(p + SM_AL) = make_uint2(l0, l1);
            }
        }
        __syncthreads();

        float c[2][4][4];
        #pragma unroll
        for (int mb = 0; mb < 2; mb++)
            #pragma unroll
            for (int i = 0; i < 4; i++)
                #pragma unroll
                for (int j = 0; j < 4; j++) c[mb][i][j] = 0.f;

        #pragma unroll
        for (int ks = 0; ks < 8; ks++) {
            uint32_t off = ks * 32;
            uint32_t ah[8], al[8], bh[8], bl[8];
            ldsm4(aA0 + SM_AH + off,            ah[0], ah[1], ah[2], ah[3]);
            ldsm4(aA0 + SM_AH + 16 * 272 + off, ah[4], ah[5], ah[6], ah[7]);
            ldsm4(aA0 + SM_AL + off,            al[0], al[1], al[2], al[3]);
            ldsm4(aA0 + SM_AL + 16 * 272 + off, al[4], al[5], al[6], al[7]);
            ldsm4(aB0 + SM_BH + off,            bh[0], bh[1], bh[2], bh[3]);
            ldsm4(aB0 + SM_BH + 16 * 272 + off, bh[4], bh[5], bh[6], bh[7]);
            ldsm4(aB0 + SM_BL + off,            bl[0], bl[1], bl[2], bl[3]);
            ldsm4(aB0 + SM_BL + 16 * 272 + off, bl[4], bl[5], bl[6], bl[7]);
            #pragma unroll
            for (int mb = 0; mb < 2; mb++) {
                #pragma unroll
                for (int ng = 0; ng < 4; ng++) {
                    int bi = (ng >> 1) * 4 + (ng & 1);
                    mma16816(c[mb][ng], ah + mb * 4, bh[bi], bh[bi + 2]);
                    mma16816(c[mb][ng], al + mb * 4, bh[bi], bh[bi + 2]);
                    mma16816(c[mb][ng], ah + mb * 4, bl[bi], bl[bi + 2]);
                }
            }
        }

        #pragma unroll
        for (int ng = 0; ng < 4; ng++) {
            int col0 = ncol + ng * 8 + 2 * (lane & 3);
            float bx = __ldg(&bias[col0]), by = __ldg(&bias[col0 + 1]);
            float sx0 = 0.f, sq0 = 0.f, sx1 = 0.f, sq1 = 0.f;
            #pragma unroll
            for (int mb = 0; mb < 2; mb++) {
                int r0g = rowblk + mrow + mb * 16 + (lane >> 2);
                float x0 = c[mb][ng][0] + bx, x1 = c[mb][ng][1] + by;
                float x2 = c[mb][ng][2] + bx, x3 = c[mb][ng][3] + by;
                *(float2*)(C + r0g * DD + col0)       = make_float2(x0, x1);
                *(float2*)(C + (r0g + 8) * DD + col0) = make_float2(x2, x3);
                sx0 += x0 + x2; sq0 += x0 * x0 + x2 * x2;
                sx1 += x1 + x3; sq1 += x1 * x1 + x3 * x3;
            }
            #pragma unroll
            for (int d = 4; d < 32; d <<= 1) {
                sx0 += __shfl_xor_sync(~0u, sx0, d);
                sq0 += __shfl_xor_sync(~0u, sq0, d);
                sx1 += __shfl_xor_sync(~0u, sx1, d);
                sq1 += __shfl_xor_sync(~0u, sq1, d);
            }
            if ((lane >> 2) == 0) {
                atomicAdd(&s_sum[col0], sx0);
                atomicAdd(&s_sum[col0 + 1], sx1);
                atomicAdd(&s_sq[col0], sq0);
                atomicAdd(&s_sq[col0 + 1], sq1);
            }
        }
        __syncthreads();
    }
    __syncthreads();
    if (tid < 128) {
        atomicAdd(&g_s2[l * DD + tid], s_sum[tid]);
        atomicAdd(&g_q2[l * DD + tid], s_sq[tid]);
    }
}

// ---------------- BN2 + (relu) + residual + fp16 shadow refresh ----------------
__global__ void residual_kernel(float4* __restrict__ h4,
                                const float* __restrict__ gamma,
                                const float* __restrict__ beta,
                                int l, int do_relu) {
    __shared__ float s_scale[128], s_shift[128];
    int tid = threadIdx.x;
    if (tid < 128) {
        const float invN = 1.0f / (float)NN;
        float m   = g_s2[l * DD + tid] * invN;
        float var = g_q2[l * DD + tid] * invN - m * m;
        float sc  = __ldg(&gamma[tid]) * rsqrtf(var + 1e-5f);
        s_scale[tid] = sc;
        s_shift[tid] = __ldg(&beta[tid]) - m * sc;
    }
    __syncthreads();
    int i = blockIdx.x * 256 + tid;
    int c4 = i & 31;
    float4 v  = *((const float4*)g_z0 + i);
    float4 sc = *(const float4*)(s_scale + c4 * 4);
    float4 sh = *(const float4*)(s_shift + c4 * 4);
    v.x = fmaf(v.x, sc.x, sh.x);
    v.y = fmaf(v.y, sc.y, sh.y);
    v.z = fmaf(v.z, sc.z, sh.z);
    v.w = fmaf(v.w, sc.w, sh.w);
    if (do_relu) {
        v.x = fmaxf(v.x, 0.f); v.y = fmaxf(v.y, 0.f);
        v.z = fmaxf(v.z, 0.f); v.w = fmaxf(v.w, 0.f);
    }
    float4 hh = h4[i];
    hh.x += v.x; hh.y += v.y; hh.z += v.z; hh.w += v.w;
    h4[i] = hh;
    ((uint2*)g_hh)[i] = f2h4(hh);
}

// ---------------- launcher ----------------
extern "C" void kernel_launch(void* const* d_in, const int* in_sizes, int n_in,
                              void* d_out, int out_size) {
    const int*   x_ids = (const int*)d_in[0];
    const int*   ei    = (const int*)d_in[1];
    const int*   eattr = (const int*)d_in[2];
    const float* atom  = (const float*)d_in[3];
    const float* bond  = (const float*)d_in[4];
    const float* W1    = (const float*)d_in[5];
    const float* b1    = (const float*)d_in[6];
    const float* g1    = (const float*)d_in[7];
    const float* bt1   = (const float*)d_in[8];
    const float* W2    = (const float*)d_in[9];
    const float* b2    = (const float*)d_in[10];
    const float* eps   = (const float*)d_in[11];
    const float* gout  = (const float*)d_in[12];
    const float* bout  = (const float*)d_in[13];
    float* h = (float*)d_out;

    cudaFuncSetAttribute(agg_gemm1_kernel, cudaFuncAttributeMaxDynamicSharedMemorySize, SMEM_FUSED);
    cudaFuncSetAttribute(gemm2_kernel,     cudaFuncAttributeMaxDynamicSharedMemorySize, SMEM_GEMM);

    embed_kernel<<<5640, 256>>>((float4*)h, x_ids, (const float4*)atom, W1, W2);    // 0
    hist_kernel<<<EE / 256, 256>>>(ei);                                             // 1
    scan_scatter_kernel<<<40, 1024>>>(ei, eattr);                                   // 2

    for (int l = 0; l < LL; l++) {
        agg_gemm1_kernel<<<296, 256, SMEM_FUSED>>>((const float4*)h, bond, eps, l,
                                                   b1 + l * DD);                    // 3 (l=0)
        gemm2_kernel<<<296, 256, SMEM_GEMM>>>(l, b2 + l * DD,
                                              g1 + l * DD, bt1 + l * DD);
        residual_kernel<<<NN * 32 / 256, 256>>>((float4*)h, gout + l * DD,
                                                bout + l * DD, l, (l < LL - 1) ? 1 : 0);
    }
    (void)in_sizes; (void)n_in; (void)out_size;
}

// round 12
// speedup vs baseline: 1.1914x; 1.1914x over previous
#include <cuda_runtime.h>
#include <cuda_fp16.h>
#include <cuda_bf16.h>
#include <cstdint>

#define NN 40000
#define EE 640000
#define DD 128
#define LL 5
#define NTILES 625          // NN / 64 (64-row GEMM tiles, exact)
#define NCTA 296            // persistent grid (2 CTAs/SM x 148)

// ---------------- device scratch (static, no allocation) ----------------
__device__ float g_z0[NN * DD];   // agg output / gemm2 output
__device__ float g_y1[NN * DD];   // gemm1 output
__device__ __half g_hh[NN * DD];  // fp16 shadow of h (gather source)
__device__ int   g_rowptr[NN + 1];
__device__ int   g_cursor[NN];
__device__ int   g_packed[EE];    // (src<<5) | (attr*32)<<21, grouped by dst
__device__ int   g_bflag[40];
__device__ int   g_bpre[40];
__device__ int   g_bar;           // scan_scatter barrier
__device__ int   g_bar2;          // layer-kernel grid barrier (zeroed per replay)
__device__ int   g_ctr[10];       // per-layer work-steal counters (2 per layer)
__device__ float g_s1[LL * DD], g_q1[LL * DD];   // BN1 stats per layer
__device__ float g_s2[LL * DD], g_q2[LL * DD];   // BN2 stats per layer
__device__ uint4 g_wth4[10 * 2048];
__device__ uint4 g_wtl4[10 * 2048];

// ---------------- helpers ----------------
__device__ __forceinline__ uint32_t smem_u32(const void* p) {
    uint32_t a;
    asm("{ .reg .u64 t; cvta.to.shared.u64 t, %1; cvt.u32.u64 %0, t; }" : "=r"(a) : "l"(p));
    return a;
}
__device__ __forceinline__ void ldsm4(uint32_t a, uint32_t& r0, uint32_t& r1,
                                      uint32_t& r2, uint32_t& r3) {
    asm volatile("ldmatrix.sync.aligned.m8n8.x4.shared.b16 {%0,%1,%2,%3}, [%4];"
                 : "=r"(r0), "=r"(r1), "=r"(r2), "=r"(r3) : "r"(a));
}
__device__ __forceinline__ void mma16816(float* c, const uint32_t* a, uint32_t b0, uint32_t b1) {
    asm volatile(
        "mma.sync.aligned.m16n8k16.row.col.f32.bf16.bf16.f32 "
        "{%0,%1,%2,%3}, {%4,%5,%6,%7}, {%8,%9}, {%0,%1,%2,%3};"
        : "+f"(c[0]), "+f"(c[1]), "+f"(c[2]), "+f"(c[3])
        : "r"(a[0]), "r"(a[1]), "r"(a[2]), "r"(a[3]), "r"(b0), "r"(b1));
}
__device__ __forceinline__ void split2(float a, float b, uint32_t& hi, uint32_t& lo) {
    __nv_bfloat16 ha = __float2bfloat16_rn(a), hb = __float2bfloat16_rn(b);
    float ra = a - __bfloat162float(ha), rb = b - __bfloat162float(hb);
    __nv_bfloat162 ph = __halves2bfloat162(ha, hb);
    __nv_bfloat162 pl = __halves2bfloat162(__float2bfloat16_rn(ra), __float2bfloat16_rn(rb));
    hi = *(uint32_t*)&ph;
    lo = *(uint32_t*)&pl;
}
__device__ __forceinline__ uint2 f2h4(float4 v) {
    __half2 lo = __floats2half2_rn(v.x, v.y);
    __half2 hi = __floats2half2_rn(v.z, v.w);
    uint2 r;
    r.x = *(unsigned*)&lo;
    r.y = *(unsigned*)&hi;
    return r;
}
__device__ __forceinline__ void msg2(uint2 r, uint2 e, __half2& m0, __half2& m1, __half2 z2) {
    m0 = __hmax2(__hadd2(*(__half2*)&r.x, *(__half2*)&e.x), z2);
    m1 = __hmax2(__hadd2(*(__half2*)&r.y, *(__half2*)&e.y), z2);
}
// grid barrier over NCTA resident CTAs (all co-resident: 2 CTAs/SM proven)
__device__ __forceinline__ void grid_sync(int target) {
    __threadfence();
    __syncthreads();
    if (threadIdx.x == 0) {
        atomicAdd(&g_bar2, 1);
        while (((volatile int*)&g_bar2)[0] < target) { }
    }
    __syncthreads();
}

// ---------------- embed + wconv + per-replay zeroing + fp16 shadow ----------------
__global__ void embed_kernel(float4* __restrict__ h4,
                             const int* __restrict__ x_ids,
                             const float4* __restrict__ atom4,
                             const float* __restrict__ W1,
                             const float* __restrict__ W2) {
    int blk = blockIdx.x;
    if (blk < 5000) {
        int i = blk * 256 + threadIdx.x;
        if (i < NN) g_cursor[i] = 0;
        if (i < 40) { g_bflag[i] = 0; g_bpre[i] = 0; }
        if (i < 10) g_ctr[i] = 0;
        if (i == 42) g_bar = 0;
        if (i == 43) g_bar2 = 0;
        if (i < LL * DD) { g_s1[i] = 0.f; g_q1[i] = 0.f; g_s2[i] = 0.f; g_q2[i] = 0.f; }
        int n = i >> 5, c = i & 31;
        float4 v = __ldg(&atom4[x_ids[n] * 32 + c]);
        h4[i] = v;
        ((uint2*)g_hh)[i] = f2h4(v);
    } else {
        int i = (blk - 5000) * 256 + threadIdx.x;   // 0..163839
        int which = i >> 14;
        int j = i & 16383;
        int n = j >> 7, k = j & 127;
        const float* W = ((which & 1) ? W2 : W1) + (which >> 1) * DD * DD;
        float v = __ldg(&W[k * DD + n]);
        __nv_bfloat16 h = __float2bfloat16_rn(v);
        float r = v - __bfloat162float(h);
        ((__nv_bfloat16*)g_wth4)[i] = h;
        ((__nv_bfloat16*)g_wtl4)[i] = __float2bfloat16_rn(r);
    }
}

// ---------------- CSR build ----------------
__global__ void hist_kernel(const int* __restrict__ ei) {
    int e = blockIdx.x * 256 + threadIdx.x;
    atomicAdd(&g_cursor[ei[EE + e]], 1);
}

__global__ void __launch_bounds__(1024) scan_scatter_kernel(const int* __restrict__ ei,
                                                            const int* __restrict__ eattr) {
    __shared__ int wsum[32];
    __shared__ int s_boff;
    int tid = threadIdx.x, lane = tid & 31, wid = tid >> 5;
    int b = blockIdx.x;
    int i = b * 1024 + tid;
    int v = (i < NN) ? g_cursor[i] : 0;
    int x = v;
    #pragma unroll
    for (int o = 1; o < 32; o <<= 1) { int t = __shfl_up_sync(~0u, x, o); if (lane >= o) x += t; }
    if (lane == 31) wsum[wid] = x;
    __syncthreads();
    if (wid == 0) {
        int y = wsum[lane];
        #pragma unroll
        for (int o = 1; o < 32; o <<= 1) { int t = __shfl_up_sync(~0u, y, o); if (lane >= o) y += t; }
        wsum[lane] = y;
    }
    __syncthreads();
    int incl = (wid ? wsum[wid - 1] : 0) + x;
    if (tid == 0) {
        int total = wsum[31];
        int p = 0;
        if (b > 0) {
            while (((volatile int*)g_bflag)[b - 1] == 0) { }
            p = ((volatile int*)g_bpre)[b - 1];
        }
        g_bpre[b] = p + total;
        __threadfence();
        ((volatile int*)g_bflag)[b] = 1;
        s_boff = p;
    }
    __syncthreads();
    int boff = s_boff;
    if (i < NN) {
        g_rowptr[i + 1] = boff + incl;
        g_cursor[i] = boff + incl - v;
    }
    if (i == 0) g_rowptr[0] = 0;
    __threadfence();
    __syncthreads();
    if (tid == 0) atomicAdd(&g_bar, 1);
    if (tid == 0) { while (((volatile int*)&g_bar)[0] < 40) { } }
    __syncthreads();
    for (int e = b * 16000 + tid; e < (b + 1) * 16000; e += 1024) {
        int d = ei[EE + e];
        int p = atomicAdd(&g_cursor[d], 1);
        g_packed[p] = (ei[e] << 5) | ((eattr[e] << 5) << 21);
    }
}

// ---------------- edge aggregation (half2 math; high-occupancy launch) ----------------
__global__ void __launch_bounds__(256) agg_kernel(const float4* __restrict__ h4,
                                                  const float* __restrict__ bond_emb,
                                                  const float* __restrict__ eps, int l) {
    __shared__ uint2 sbe2[4 * 32];
    int tid = threadIdx.x;
    if (tid < 128) {
        float4 v = __ldg((const float4*)(bond_emb + l * 512) + tid);
        sbe2[tid] = f2h4(v);
    }
    __syncthreads();
    int lane = tid & 31;
    int v = blockIdx.x * 8 + (tid >> 5);
    float ep = 1.0f + __ldg(&eps[l]);
    const uint2* hh2 = (const uint2*)g_hh;
    float4 hv = __ldg(&h4[v * 32 + lane]);
    float4 acc = make_float4(hv.x * ep, hv.y * ep, hv.z * ep, hv.w * ep);
    const __half2 z2 = __float2half2_rn(0.f);
    int start = g_rowptr[v], end = g_rowptr[v + 1];
    for (int base = start; base < end; base += 32) {
        int nl = min(32, end - base);
        int pk = (base + lane < end) ? g_packed[base + lane] : 0;
        int j = 0;
        for (; j + 4 <= nl; j += 4) {
            int p0 = __shfl_sync(~0u, pk, j);
            int p1 = __shfl_sync(~0u, pk, j + 1);
            int p2 = __shfl_sync(~0u, pk, j + 2);
            int p3 = __shfl_sync(~0u, pk, j + 3);
            uint2 r0 = __ldg(&hh2[(p0 & 0x1FFFFF) + lane]);
            uint2 r1 = __ldg(&hh2[(p1 & 0x1FFFFF) + lane]);
            uint2 r2 = __ldg(&hh2[(p2 & 0x1FFFFF) + lane]);
            uint2 r3 = __ldg(&hh2[(p3 & 0x1FFFFF) + lane]);
            uint2 e0 = sbe2[((unsigned)p0 >> 21) + lane];
            uint2 e1 = sbe2[((unsigned)p1 >> 21) + lane];
            uint2 e2 = sbe2[((unsigned)p2 >> 21) + lane];
            uint2 e3 = sbe2[((unsigned)p3 >> 21) + lane];
            __half2 a0, a1, b0, b1, m0, m1;
            msg2(r0, e0, a0, a1, z2);
            msg2(r1, e1, b0, b1, z2);
            msg2(r2, e2, m0, m1, z2);
            a0 = __hadd2(a0, m0); a1 = __hadd2(a1, m1);
            msg2(r3, e3, m0, m1, z2);
            b0 = __hadd2(b0, m0); b1 = __hadd2(b1, m1);
            float2 fa0 = __half22float2(a0), fa1 = __half22float2(a1);
            float2 fb0 = __half22float2(b0), fb1 = __half22float2(b1);
            acc.x += fa0.x + fb0.x;
            acc.y += fa0.y + fb0.y;
            acc.z += fa1.x + fb1.x;
            acc.w += fa1.y + fb1.y;
        }
        for (; j < nl; j++) {
            int p0 = __shfl_sync(~0u, pk, j);
            uint2 r0 = __ldg(&hh2[(p0 & 0x1FFFFF) + lane]);
            uint2 e0 = sbe2[((unsigned)p0 >> 21) + lane];
            __half2 m0, m1;
            msg2(r0, e0, m0, m1, z2);
            float2 f0 = __half22float2(m0), f1 = __half22float2(m1);
            acc.x += f0.x; acc.y += f0.y; acc.z += f1.x; acc.w += f1.y;
        }
    }
    *((float4*)g_z0 + v * 32 + lane) = acc;
}

// ---------------- smem layout ----------------
#define SM_AH    0
#define SM_AL    17408
#define SM_BH    34816
#define SM_BL    69632
#define SM_SUM   104448
#define SM_SQ    104960
#define SM_SCALE 105472
#define SM_SHIFT 105984
#define SM_TILE  106496
#define SMEM_GEMM 106512

// ---------------- one GEMM phase (work-stealing over 625 tiles) ----------------
template <bool TRANS>
__device__ __forceinline__ void gemm_phase(char* smem, uint32_t sb,
                                           const float* __restrict__ A, float* __restrict__ C,
                                           int which, const float* __restrict__ bias,
                                           int* ctr, float* gs, float* gq) {
    float* s_sum   = (float*)(smem + SM_SUM);
    float* s_sq    = (float*)(smem + SM_SQ);
    float* s_scale = (float*)(smem + SM_SCALE);
    float* s_shift = (float*)(smem + SM_SHIFT);
    int*   s_tile  = (int*)(smem + SM_TILE);
    int tid = threadIdx.x, lane = tid & 31, wid = tid >> 5;
    if (tid < 128) { s_sum[tid] = 0.f; s_sq[tid] = 0.f; }
    {   // stage B (hi/lo bf16)
        const uint4* srcH = g_wth4 + which * 2048;
        const uint4* srcL = g_wtl4 + which * 2048;
        #pragma unroll
        for (int it = 0; it < 8; it++) {
            int s = it * 256 + tid;
            int row = s >> 4, ch = s & 15;
            *(uint4*)(smem + SM_BH + row * 272 + ch * 16) = __ldg(&srcH[row * 16 + ch]);
            *(uint4*)(smem + SM_BL + row * 272 + ch * 16) = __ldg(&srcL[row * 16 + ch]);
        }
    }
    int mrow = (wid & 1) * 32;
    int ncol = (wid >> 1) * 32;
    int gm = lane & 7, gh = (lane >> 3) & 1, gk = lane >> 4;
    uint32_t aA0 = sb + (mrow + gm + gh * 8) * 272 + gk * 16;
    uint32_t aB0 = sb + (ncol + gm + gh * 8) * 272 + gk * 16;
    int ar = tid >> 5, ac4 = tid & 31;

    for (;;) {
        if (tid == 0) *s_tile = atomicAdd(ctr, 1);
        __syncthreads();
        int t = *s_tile;
        if (t >= NTILES) break;
        int rowblk = t * 64;

        {   // stage A tile, optional BN+relu, bf16 hi/lo split
            float4 sc, sh;
            if (TRANS) {
                sc = *(const float4*)(s_scale + ac4 * 4);
                sh = *(const float4*)(s_shift + ac4 * 4);
            }
            #pragma unroll
            for (int i = 0; i < 8; i++) {
                int rr = ar + i * 8;
                float4 v = __ldg((const float4*)(A + (rowblk + rr) * DD) + ac4);
                if (TRANS) {
                    v.x = fmaxf(fmaf(v.x, sc.x, sh.x), 0.f);
                    v.y = fmaxf(fmaf(v.y, sc.y, sh.y), 0.f);
                    v.z = fmaxf(fmaf(v.z, sc.z, sh.z), 0.f);
                    v.w = fmaxf(fmaf(v.w, sc.w, sh.w), 0.f);
                }
                uint32_t h0, l0, h1, l1;
                split2(v.x, v.y, h0, l0);
                split2(v.z, v.w, h1, l1);
                char* p = smem + rr * 272 + ac4 * 8;
                *(uint2*)(p + SM_AH) = make_uint2(h0, h1);
                *(uint2*)(p + SM_AL) = make_uint2(l0, l1);
            }
        }
        __syncthreads();

        float c[2][4][4];
        #pragma unroll
        for (int mb = 0; mb < 2; mb++)
            #pragma unroll
            for (int i = 0; i < 4; i++)
                #pragma unroll
                for (int j = 0; j < 4; j++) c[mb][i][j] = 0.f;

        #pragma unroll
        for (int ks = 0; ks < 8; ks++) {
            uint32_t off = ks * 32;
            uint32_t ah[8], al[8], bh[8], bl[8];
            ldsm4(aA0 + SM_AH + off,            ah[0], ah[1], ah[2], ah[3]);
            ldsm4(aA0 + SM_AH + 16 * 272 + off, ah[4], ah[5], ah[6], ah[7]);
            ldsm4(aA0 + SM_AL + off,            al[0], al[1], al[2], al[3]);
            ldsm4(aA0 + SM_AL + 16 * 272 + off, al[4], al[5], al[6], al[7]);
            ldsm4(aB0 + SM_BH + off,            bh[0], bh[1], bh[2], bh[3]);
            ldsm4(aB0 + SM_BH + 16 * 272 + off, bh[4], bh[5], bh[6], bh[7]);
            ldsm4(aB0 + SM_BL + off,            bl[0], bl[1], bl[2], bl[3]);
            ldsm4(aB0 + SM_BL + 16 * 272 + off, bl[4], bl[5], bl[6], bl[7]);
            #pragma unroll
            for (int mb = 0; mb < 2; mb++) {
                #pragma unroll
                for (int ng = 0; ng < 4; ng++) {
                    int bi = (ng >> 1) * 4 + (ng & 1);
                    mma16816(c[mb][ng], ah + mb * 4, bh[bi], bh[bi + 2]);
                    mma16816(c[mb][ng], al + mb * 4, bh[bi], bh[bi + 2]);
                    mma16816(c[mb][ng], ah + mb * 4, bl[bi], bl[bi + 2]);
                }
            }
        }

        #pragma unroll
        for (int ng = 0; ng < 4; ng++) {
            int col0 = ncol + ng * 8 + 2 * (lane & 3);
            float bx = __ldg(&bias[col0]), by = __ldg(&bias[col0 + 1]);
            float sx0 = 0.f, sq0 = 0.f, sx1 = 0.f, sq1 = 0.f;
            #pragma unroll
            for (int mb = 0; mb < 2; mb++) {
                int r0g = rowblk + mrow + mb * 16 + (lane >> 2);
                float x0 = c[mb][ng][0] + bx, x1 = c[mb][ng][1] + by;
                float x2 = c[mb][ng][2] + bx, x3 = c[mb][ng][3] + by;
                *(float2*)(C + r0g * DD + col0)       = make_float2(x0, x1);
                *(float2*)(C + (r0g + 8) * DD + col0) = make_float2(x2, x3);
                sx0 += x0 + x2; sq0 += x0 * x0 + x2 * x2;
                sx1 += x1 + x3; sq1 += x1 * x1 + x3 * x3;
            }
            #pragma unroll
            for (int d = 4; d < 32; d <<= 1) {
                sx0 += __shfl_xor_sync(~0u, sx0, d);
                sq0 += __shfl_xor_sync(~0u, sq0, d);
                sx1 += __shfl_xor_sync(~0u, sx1, d);
                sq1 += __shfl_xor_sync(~0u, sq1, d);
            }
            if ((lane >> 2) == 0) {
                atomicAdd(&s_sum[col0], sx0);
                atomicAdd(&s_sum[col0 + 1], sx1);
                atomicAdd(&s_sq[col0], sq0);
                atomicAdd(&s_sq[col0 + 1], sq1);
            }
        }
        __syncthreads();
    }
    __syncthreads();
    if (tid < 128) {
        atomicAdd(&gs[tid], s_sum[tid]);
        atomicAdd(&gq[tid], s_sq[tid]);
    }
}

// ---------------- persistent layer kernel: gemm1 -> BN1 -> gemm2 -> BN2 -> residual ----------------
__global__ void __launch_bounds__(256, 2) layer_kernel(float4* __restrict__ h4, int l,
                                                       const float* __restrict__ b1p,
                                                       const float* __restrict__ g1p,
                                                       const float* __restrict__ bt1p,
                                                       const float* __restrict__ b2p,
                                                       const float* __restrict__ goutp,
                                                       const float* __restrict__ boutp,
                                                       int do_relu) {
    extern __shared__ char smem[];
    uint32_t sb = smem_u32(smem);
    float* s_scale = (float*)(smem + SM_SCALE);
    float* s_shift = (float*)(smem + SM_SHIFT);
    int tid = threadIdx.x;
    const float invN = 1.0f / (float)NN;

    // phase 1: y1 = z0 @ W1 + b1, stats -> g_s1/g_q1
    gemm_phase<false>(smem, sb, g_z0, g_y1, l * 2, b1p,
                      &g_ctr[l * 2], &g_s1[l * DD], &g_q1[l * DD]);
    grid_sync(NCTA * (2 * l + 1));

    if (tid < 128) {   // BN1 scale/shift (cross-CTA stats via L2)
        float m   = __ldcg(&g_s1[l * DD + tid]) * invN;
        float var = __ldcg(&g_q1[l * DD + tid]) * invN - m * m;
        float sc  = __ldg(&g1p[tid]) * rsqrtf(var + 1e-5f);
        s_scale[tid] = sc;
        s_shift[tid] = __ldg(&bt1p[tid]) - m * sc;
    }
    __syncthreads();

    // phase 2: z0 = relu(BN1(y1)) @ W2 + b2, stats -> g_s2/g_q2
    gemm_phase<true>(smem, sb, g_y1, g_z0, l * 2 + 1, b2p,
                     &g_ctr[l * 2 + 1], &g_s2[l * DD], &g_q2[l * DD]);
    grid_sync(NCTA * (2 * l + 2));

    if (tid < 128) {   // BN2 scale/shift
        float m   = __ldcg(&g_s2[l * DD + tid]) * invN;
        float var = __ldcg(&g_q2[l * DD + tid]) * invN - m * m;
        float sc  = __ldg(&goutp[tid]) * rsqrtf(var + 1e-5f);
        s_scale[tid] = sc;
        s_shift[tid] = __ldg(&boutp[tid]) - m * sc;
    }
    __syncthreads();

    // phase 3: h += act(BN2(z0)); refresh fp16 shadow
    for (int i = blockIdx.x * 256 + tid; i < NN * 32; i += NCTA * 256) {
        int c4 = i & 31;
        float4 v  = *((const float4*)g_z0 + i);
        float4 sc = *(const float4*)(s_scale + c4 * 4);
        float4 sh = *(const float4*)(s_shift + c4 * 4);
        v.x = fmaf(v.x, sc.x, sh.x);
        v.y = fmaf(v.y, sc.y, sh.y);
        v.z = fmaf(v.z, sc.z, sh.z);
        v.w = fmaf(v.w, sc.w, sh.w);
        if (do_relu) {
            v.x = fmaxf(v.x, 0.f); v.y = fmaxf(v.y, 0.f);
            v.z = fmaxf(v.z, 0.f); v.w = fmaxf(v.w, 0.f);
        }
        float4 hh = h4[i];
        hh.x += v.x; hh.y += v.y; hh.z += v.z; hh.w += v.w;
        h4[i] = hh;
        ((uint2*)g_hh)[i] = f2h4(hh);
    }
}

// ---------------- launcher ----------------
extern "C" void kernel_launch(void* const* d_in, const int* in_sizes, int n_in,
                              void* d_out, int out_size) {
    const int*   x_ids = (const int*)d_in[0];
    const int*   ei    = (const int*)d_in[1];
    const int*   eattr = (const int*)d_in[2];
    const float* atom  = (const float*)d_in[3];
    const float* bond  = (const float*)d_in[4];
    const float* W1    = (const float*)d_in[5];
    const float* b1    = (const float*)d_in[6];
    const float* g1    = (const float*)d_in[7];
    const float* bt1   = (const float*)d_in[8];
    const float* W2    = (const float*)d_in[9];
    const float* b2    = (const float*)d_in[10];
    const float* eps   = (const float*)d_in[11];
    const float* gout  = (const float*)d_in[12];
    const float* bout  = (const float*)d_in[13];
    float* h = (float*)d_out;

    cudaFuncSetAttribute(layer_kernel, cudaFuncAttributeMaxDynamicSharedMemorySize, SMEM_GEMM);

    embed_kernel<<<5640, 256>>>((float4*)h, x_ids, (const float4*)atom, W1, W2);    // 0
    hist_kernel<<<EE / 256, 256>>>(ei);                                             // 1
    scan_scatter_kernel<<<40, 1024>>>(ei, eattr);                                   // 2

    for (int l = 0; l < LL; l++) {
        agg_kernel<<<NN / 8, 256>>>((const float4*)h, bond, eps, l);                // 3 (l=0)
        layer_kernel<<<NCTA, 256, SMEM_GEMM>>>((float4*)h, l,
                                               b1 + l * DD, g1 + l * DD, bt1 + l * DD,
                                               b2 + l * DD, gout + l * DD, bout + l * DD,
                                               (l < LL - 1) ? 1 : 0);
    }
    (void)in_sizes; (void)n_in; (void)out_size;
}

// round 13
// speedup vs baseline: 1.2088x; 1.0146x over previous
#include <cuda_runtime.h>
#include <cuda_fp16.h>
#include <cuda_bf16.h>
#include <cstdint>

#define NN 40000
#define EE 640000
#define DD 128
#define LL 5
#define NTILES 625          // NN / 64 (64-row GEMM tiles, exact)

// ---------------- device scratch (static, no allocation) ----------------
__device__ float g_z0[NN * DD];   // agg output / gemm2 output
__device__ float g_y1[NN * DD];   // gemm1 output
__device__ __half g_hh[NN * DD];  // fp16 shadow of h (gather source)
__device__ int   g_rowptr[NN + 1];
__device__ int   g_cursor[NN];
__device__ int   g_packed[EE];    // (src<<5) | (attr*32)<<21, grouped by dst
__device__ int   g_bflag[40];
__device__ int   g_bpre[40];
__device__ int   g_bar;
__device__ int   g_ctr[2];        // work-stealing counters (gemm1, gemm2)
__device__ float g_sum1[DD], g_sq1[DD];   // stats of gemm1 output (BN1)
__device__ float g_sum2[DD], g_sq2[DD];   // stats of gemm2 output (BN2)
__device__ uint4 g_wth4[10 * 2048];
__device__ uint4 g_wtl4[10 * 2048];

// ---------------- helpers ----------------
__device__ __forceinline__ uint32_t smem_u32(const void* p) {
    uint32_t a;
    asm("{ .reg .u64 t; cvta.to.shared.u64 t, %1; cvt.u32.u64 %0, t; }" : "=r"(a) : "l"(p));
    return a;
}
__device__ __forceinline__ void ldsm4(uint32_t a, uint32_t& r0, uint32_t& r1,
                                      uint32_t& r2, uint32_t& r3) {
    asm volatile("ldmatrix.sync.aligned.m8n8.x4.shared.b16 {%0,%1,%2,%3}, [%4];"
                 : "=r"(r0), "=r"(r1), "=r"(r2), "=r"(r3) : "r"(a));
}
__device__ __forceinline__ void mma16816(float* c, const uint32_t* a, uint32_t b0, uint32_t b1) {
    asm volatile(
        "mma.sync.aligned.m16n8k16.row.col.f32.bf16.bf16.f32 "
        "{%0,%1,%2,%3}, {%4,%5,%6,%7}, {%8,%9}, {%0,%1,%2,%3};"
        : "+f"(c[0]), "+f"(c[1]), "+f"(c[2]), "+f"(c[3])
        : "r"(a[0]), "r"(a[1]), "r"(a[2]), "r"(a[3]), "r"(b0), "r"(b1));
}
__device__ __forceinline__ void split2(float a, float b, uint32_t& hi, uint32_t& lo) {
    __nv_bfloat16 ha = __float2bfloat16_rn(a), hb = __float2bfloat16_rn(b);
    float ra = a - __bfloat162float(ha), rb = b - __bfloat162float(hb);
    __nv_bfloat162 ph = __halves2bfloat162(ha, hb);
    __nv_bfloat162 pl = __halves2bfloat162(__float2bfloat16_rn(ra), __float2bfloat16_rn(rb));
    hi = *(uint32_t*)&ph;
    lo = *(uint32_t*)&pl;
}
__device__ __forceinline__ uint2 f2h4(float4 v) {
    __half2 lo = __floats2half2_rn(v.x, v.y);
    __half2 hi = __floats2half2_rn(v.z, v.w);
    uint2 r;
    r.x = *(unsigned*)&lo;
    r.y = *(unsigned*)&hi;
    return r;
}
__device__ __forceinline__ void msg2(uint2 r, uint2 e, __half2& m0, __half2& m1, __half2 z2) {
    m0 = __hmax2(__hadd2(*(__half2*)&r.x, *(__half2*)&e.x), z2);
    m1 = __hmax2(__hadd2(*(__half2*)&r.y, *(__half2*)&e.y), z2);
}

// ---------------- embed + wconv + per-replay zeroing + fp16 shadow ----------------
__global__ void embed_kernel(float4* __restrict__ h4,
                             const int* __restrict__ x_ids,
                             const float4* __restrict__ atom4,
                             const float* __restrict__ W1,
                             const float* __restrict__ W2) {
    int blk = blockIdx.x;
    if (blk < 5000) {
        int i = blk * 256 + threadIdx.x;
        if (i < NN) g_cursor[i] = 0;
        if (i < 40) { g_bflag[i] = 0; g_bpre[i] = 0; }
        if (i < 2) g_ctr[i] = 0;
        if (i == 42) g_bar = 0;
        int n = i >> 5, c = i & 31;
        float4 v = __ldg(&atom4[x_ids[n] * 32 + c]);
        h4[i] = v;
        ((uint2*)g_hh)[i] = f2h4(v);
    } else {
        int i = (blk - 5000) * 256 + threadIdx.x;   // 0..163839
        int which = i >> 14;
        int j = i & 16383;
        int n = j >> 7, k = j & 127;
        const float* W = ((which & 1) ? W2 : W1) + (which >> 1) * DD * DD;
        float v = __ldg(&W[k * DD + n]);
        __nv_bfloat16 h = __float2bfloat16_rn(v);
        float r = v - __bfloat162float(h);
        ((__nv_bfloat16*)g_wth4)[i] = h;
        ((__nv_bfloat16*)g_wtl4)[i] = __float2bfloat16_rn(r);
    }
}

// ---------------- CSR build ----------------
__global__ void hist_kernel(const int* __restrict__ ei) {
    int e = blockIdx.x * 256 + threadIdx.x;
    atomicAdd(&g_cursor[ei[EE + e]], 1);
}

__global__ void __launch_bounds__(1024) scan_scatter_kernel(const int* __restrict__ ei,
                                                            const int* __restrict__ eattr) {
    __shared__ int wsum[32];
    __shared__ int s_boff;
    int tid = threadIdx.x, lane = tid & 31, wid = tid >> 5;
    int b = blockIdx.x;
    int i = b * 1024 + tid;
    int v = (i < NN) ? g_cursor[i] : 0;
    int x = v;
    #pragma unroll
    for (int o = 1; o < 32; o <<= 1) { int t = __shfl_up_sync(~0u, x, o); if (lane >= o) x += t; }
    if (lane == 31) wsum[wid] = x;
    __syncthreads();
    if (wid == 0) {
        int y = wsum[lane];
        #pragma unroll
        for (int o = 1; o < 32; o <<= 1) { int t = __shfl_up_sync(~0u, y, o); if (lane >= o) y += t; }
        wsum[lane] = y;
    }
    __syncthreads();
    int incl = (wid ? wsum[wid - 1] : 0) + x;
    if (tid == 0) {
        int total = wsum[31];
        int p = 0;
        if (b > 0) {
            while (((volatile int*)g_bflag)[b - 1] == 0) { }
            p = ((volatile int*)g_bpre)[b - 1];
        }
        g_bpre[b] = p + total;
        __threadfence();
        ((volatile int*)g_bflag)[b] = 1;
        s_boff = p;
    }
    __syncthreads();
    int boff = s_boff;
    if (i < NN) {
        g_rowptr[i + 1] = boff + incl;
        g_cursor[i] = boff + incl - v;
    }
    if (i == 0) g_rowptr[0] = 0;
    __threadfence();
    __syncthreads();
    if (tid == 0) atomicAdd(&g_bar, 1);
    if (tid == 0) { while (((volatile int*)&g_bar)[0] < 40) { } }
    __syncthreads();
    for (int e = b * 16000 + tid; e < (b + 1) * 16000; e += 1024) {
        int d = ei[EE + e];
        int p = atomicAdd(&g_cursor[d], 1);
        g_packed[p] = (ei[e] << 5) | ((eattr[e] << 5) << 21);
    }
}

// ---------------- edge aggregation (half2 math, fp32 accum via 4-edge flush) ----------------
__global__ void __launch_bounds__(256) agg_kernel(const float4* __restrict__ h4,
                                                  const float* __restrict__ bond_emb,
                                                  const float* __restrict__ eps, int l) {
    __shared__ uint2 sbe2[4 * 32];
    int tid = threadIdx.x;
    if (blockIdx.x == 0 && tid < 128) {
        g_sum1[tid] = 0.f; g_sq1[tid] = 0.f;
        g_sum2[tid] = 0.f; g_sq2[tid] = 0.f;
        if (tid < 2) g_ctr[tid] = 0;
    }
    if (tid < 128) {
        float4 v = __ldg((const float4*)(bond_emb + l * 512) + tid);
        sbe2[tid] = f2h4(v);
    }
    __syncthreads();
    int lane = tid & 31;
    int v = blockIdx.x * 8 + (tid >> 5);
    float ep = 1.0f + __ldg(&eps[l]);
    const uint2* hh2 = (const uint2*)g_hh;
    float4 hv = __ldg(&h4[v * 32 + lane]);
    float4 acc = make_float4(hv.x * ep, hv.y * ep, hv.z * ep, hv.w * ep);
    const __half2 z2 = __float2half2_rn(0.f);
    int start = g_rowptr[v], end = g_rowptr[v + 1];
    for (int base = start; base < end; base += 32) {
        int nl = min(32, end - base);
        int pk = (base + lane < end) ? g_packed[base + lane] : 0;
        int j = 0;
        for (; j + 4 <= nl; j += 4) {
            int p0 = __shfl_sync(~0u, pk, j);
            int p1 = __shfl_sync(~0u, pk, j + 1);
            int p2 = __shfl_sync(~0u, pk, j + 2);
            int p3 = __shfl_sync(~0u, pk, j + 3);
            uint2 r0 = __ldg(&hh2[(p0 & 0x1FFFFF) + lane]);
            uint2 r1 = __ldg(&hh2[(p1 & 0x1FFFFF) + lane]);
            uint2 r2 = __ldg(&hh2[(p2 & 0x1FFFFF) + lane]);
            uint2 r3 = __ldg(&hh2[(p3 & 0x1FFFFF) + lane]);
            uint2 e0 = sbe2[((unsigned)p0 >> 21) + lane];
            uint2 e1 = sbe2[((unsigned)p1 >> 21) + lane];
            uint2 e2 = sbe2[((unsigned)p2 >> 21) + lane];
            uint2 e3 = sbe2[((unsigned)p3 >> 21) + lane];
            __half2 a0, a1, b0, b1, m0, m1;
            msg2(r0, e0, a0, a1, z2);
            msg2(r1, e1, b0, b1, z2);
            msg2(r2, e2, m0, m1, z2);
            a0 = __hadd2(a0, m0); a1 = __hadd2(a1, m1);
            msg2(r3, e3, m0, m1, z2);
            b0 = __hadd2(b0, m0); b1 = __hadd2(b1, m1);
            float2 fa0 = __half22float2(a0), fa1 = __half22float2(a1);
            float2 fb0 = __half22float2(b0), fb1 = __half22float2(b1);
            acc.x += fa0.x + fb0.x;
            acc.y += fa0.y + fb0.y;
            acc.z += fa1.x + fb1.x;
            acc.w += fa1.y + fb1.y;
        }
        for (; j < nl; j++) {
            int p0 = __shfl_sync(~0u, pk, j);
            uint2 r0 = __ldg(&hh2[(p0 & 0x1FFFFF) + lane]);
            uint2 e0 = sbe2[((unsigned)p0 >> 21) + lane];
            __half2 m0, m1;
            msg2(r0, e0, m0, m1, z2);
            float2 f0 = __half22float2(m0), f1 = __half22float2(m1);
            acc.x += f0.x; acc.y += f0.y; acc.z += f1.x; acc.w += f1.y;
        }
    }
    *((float4*)g_z0 + v * 32 + lane) = acc;
}

// ---------------- tensor-core GEMM (mma.sync bf16, 3-term split, k-loop pipelined) ----------------
// CTA tile 64x128, 256 threads = 8 warps as 2m x 4n, warp tile m32 x n32.
// 272-byte row stride; 2 CTAs/SM at 106512 B smem.
#define SM_AH    0
#define SM_AL    17408
#define SM_BH    34816
#define SM_BL    69632
#define SM_SUM   104448
#define SM_SQ    104960
#define SM_SCALE 105472
#define SM_SHIFT 105984
#define SM_TILE  106496
#define SMEM_GEMM 106512

#define LDK(buf, off)                                                                   \
    ldsm4(aA0 + SM_AH + (off),            ah[buf][0], ah[buf][1], ah[buf][2], ah[buf][3]); \
    ldsm4(aA0 + SM_AH + 16 * 272 + (off), ah[buf][4], ah[buf][5], ah[buf][6], ah[buf][7]); \
    ldsm4(aA0 + SM_AL + (off),            al[buf][0], al[buf][1], al[buf][2], al[buf][3]); \
    ldsm4(aA0 + SM_AL + 16 * 272 + (off), al[buf][4], al[buf][5], al[buf][6], al[buf][7]); \
    ldsm4(aB0 + SM_BH + (off),            bh[buf][0], bh[buf][1], bh[buf][2], bh[buf][3]); \
    ldsm4(aB0 + SM_BH + 16 * 272 + (off), bh[buf][4], bh[buf][5], bh[buf][6], bh[buf][7]); \
    ldsm4(aB0 + SM_BL + (off),            bl[buf][0], bl[buf][1], bl[buf][2], bl[buf][3]); \
    ldsm4(aB0 + SM_BL + 16 * 272 + (off), bl[buf][4], bl[buf][5], bl[buf][6], bl[buf][7]);

template <bool TRANS>
__global__ void __launch_bounds__(256, 2) gemm_kernel(int which,
                                                      const float* __restrict__ bias,
                                                      const float* __restrict__ gamma,
                                                      const float* __restrict__ beta,
                                                      int ctr_idx) {
    extern __shared__ char smem[];
    uint32_t sb = smem_u32(smem);
    float* s_sum   = (float*)(smem + SM_SUM);
    float* s_sq    = (float*)(smem + SM_SQ);
    float* s_scale = (float*)(smem + SM_SCALE);
    float* s_shift = (float*)(smem + SM_SHIFT);
    int*   s_tile  = (int*)(smem + SM_TILE);
    const float* A = TRANS ? g_y1 : g_z0;
    float* C       = TRANS ? g_z0 : g_y1;

    int tid = threadIdx.x, lane = tid & 31, wid = tid >> 5;
    if (tid < 128) {
        s_sum[tid] = 0.f; s_sq[tid] = 0.f;
        if (TRANS) {
            const float invN = 1.0f / (float)NN;
            float m   = g_sum1[tid] * invN;
            float var = g_sq1[tid] * invN - m * m;
            float sc  = __ldg(&gamma[tid]) * rsqrtf(var + 1e-5f);
            s_scale[tid] = sc;
            s_shift[tid] = __ldg(&beta[tid]) - m * sc;
        }
    }
    {   // stage B (hi/lo bf16, [n][k] -> padded smem), once per CTA
        const uint4* srcH = g_wth4 + which * 2048;
        const uint4* srcL = g_wtl4 + which * 2048;
        #pragma unroll
        for (int it = 0; it < 8; it++) {
            int s = it * 256 + tid;
            int row = s >> 4, ch = s & 15;
            *(uint4*)(smem + SM_BH + row * 272 + ch * 16) = __ldg(&srcH[row * 16 + ch]);
            *(uint4*)(smem + SM_BL + row * 272 + ch * 16) = __ldg(&srcL[row * 16 + ch]);
        }
    }

    int mrow = (wid & 1) * 32;
    int ncol = (wid >> 1) * 32;
    int gm = lane & 7, gh = (lane >> 3) & 1, gk = lane >> 4;
    uint32_t aA0 = sb + (mrow + gm + gh * 8) * 272 + gk * 16;
    uint32_t aB0 = sb + (ncol + gm + gh * 8) * 272 + gk * 16;
    int ar = tid >> 5, ac4 = tid & 31;

    for (;;) {
        if (tid == 0) *s_tile = atomicAdd(&g_ctr[ctr_idx], 1);
        __syncthreads();
        int t = *s_tile;
        if (t >= NTILES) break;
        int rowblk = t * 64;

        {   // stage A tile (64 rows x 128), optional BN1+relu, bf16 hi/lo split
            float4 sc, sh;
            if (TRANS) {
                sc = *(const float4*)(s_scale + ac4 * 4);
                sh = *(const float4*)(s_shift + ac4 * 4);
            }
            #pragma unroll
            for (int i = 0; i < 8; i++) {
                int rr = ar + i * 8;
                float4 v = __ldg((const float4*)(A + (rowblk + rr) * DD) + ac4);
                if (TRANS) {
                    v.x = fmaxf(fmaf(v.x, sc.x, sh.x), 0.f);
                    v.y = fmaxf(fmaf(v.y, sc.y, sh.y), 0.f);
                    v.z = fmaxf(fmaf(v.z, sc.z, sh.z), 0.f);
                    v.w = fmaxf(fmaf(v.w, sc.w, sh.w), 0.f);
                }
                uint32_t h0, l0, h1, l1;
                split2(v.x, v.y, h0, l0);
                split2(v.z, v.w, h1, l1);
                char* p = smem + rr * 272 + ac4 * 8;
                *(uint2*)(p + SM_AH) = make_uint2(h0, h1);
                *(uint2*)(p + SM_AL) = make_uint2(l0, l1);
            }
        }
        __syncthreads();

        float c[2][4][4];
        #pragma unroll
        for (int mb = 0; mb < 2; mb++)
            #pragma unroll
            for (int i = 0; i < 4; i++)
                #pragma unroll
                for (int j = 0; j < 4; j++) c[mb][i][j] = 0.f;

        // software-pipelined k-loop: ldsm for ks+1 issued before MMAs of ks
        uint32_t ah[2][8], al[2][8], bh[2][8], bl[2][8];
        LDK(0, 0)
        #pragma unroll
        for (int ks = 0; ks < 8; ks++) {
            const int cur = ks & 1;
            if (ks < 7) {
                const int nxt = cur ^ 1;
                uint32_t off = (ks + 1) * 32;
                LDK(nxt, off)
            }
            #pragma unroll
            for (int mb = 0; mb < 2; mb++) {
                #pragma unroll
                for (int ng = 0; ng < 4; ng++) {
                    int bi = (ng >> 1) * 4 + (ng & 1);
                    mma16816(c[mb][ng], ah[cur] + mb * 4, bh[cur][bi], bh[cur][bi + 2]);
                    mma16816(c[mb][ng], al[cur] + mb * 4, bh[cur][bi], bh[cur][bi + 2]);
                    mma16816(c[mb][ng], ah[cur] + mb * 4, bl[cur][bi], bl[cur][bi + 2]);
                }
            }
        }

        // epilogue: bias, store C, column stats (shfl-reduced)
        #pragma unroll
        for (int ng = 0; ng < 4; ng++) {
            int col0 = ncol + ng * 8 + 2 * (lane & 3);
            float bx = __ldg(&bias[col0]), by = __ldg(&bias[col0 + 1]);
            float sx0 = 0.f, sq0 = 0.f, sx1 = 0.f, sq1 = 0.f;
            #pragma unroll
            for (int mb = 0; mb < 2; mb++) {
                int r0g = rowblk + mrow + mb * 16 + (lane >> 2);
                float x0 = c[mb][ng][0] + bx, x1 = c[mb][ng][1] + by;
                float x2 = c[mb][ng][2] + bx, x3 = c[mb][ng][3] + by;
                *(float2*)(C + r0g * DD + col0)       = make_float2(x0, x1);
                *(float2*)(C + (r0g + 8) * DD + col0) = make_float2(x2, x3);
                sx0 += x0 + x2; sq0 += x0 * x0 + x2 * x2;
                sx1 += x1 + x3; sq1 += x1 * x1 + x3 * x3;
            }
            #pragma unroll
            for (int d = 4; d < 32; d <<= 1) {
                sx0 += __shfl_xor_sync(~0u, sx0, d);
                sq0 += __shfl_xor_sync(~0u, sq0, d);
                sx1 += __shfl_xor_sync(~0u, sx1, d);
                sq1 += __shfl_xor_sync(~0u, sq1, d);
            }
            if ((lane >> 2) == 0) {
                atomicAdd(&s_sum[col0], sx0);
                atomicAdd(&s_sum[col0 + 1], sx1);
                atomicAdd(&s_sq[col0], sq0);
                atomicAdd(&s_sq[col0 + 1], sq1);
            }
        }
        __syncthreads();
    }
    __syncthreads();
    if (tid < 128) {
        if (TRANS) {
            atomicAdd(&g_sum2[tid], s_sum[tid]);
            atomicAdd(&g_sq2[tid],  s_sq[tid]);
        } else {
            atomicAdd(&g_sum1[tid], s_sum[tid]);
            atomicAdd(&g_sq1[tid],  s_sq[tid]);
        }
    }
}

// ---------------- BN2 + (relu) + residual + fp16 shadow refresh ----------------
__global__ void residual_kernel(float4* __restrict__ h4,
                                const float* __restrict__ gamma,
                                const float* __restrict__ beta,
                                int do_relu) {
    __shared__ float s_scale[128], s_shift[128];
    int tid = threadIdx.x;
    if (tid < 128) {
        const float invN = 1.0f / (float)NN;
        float m   = g_sum2[tid] * invN;
        float var = g_sq2[tid] * invN - m * m;
        float sc  = __ldg(&gamma[tid]) * rsqrtf(var + 1e-5f);
        s_scale[tid] = sc;
        s_shift[tid] = __ldg(&beta[tid]) - m * sc;
    }
    __syncthreads();
    int i = blockIdx.x * 256 + tid;
    int c4 = i & 31;
    float4 v  = *((const float4*)g_z0 + i);
    float4 sc = *(const float4*)(s_scale + c4 * 4);
    float4 sh = *(const float4*)(s_shift + c4 * 4);
    v.x = fmaf(v.x, sc.x, sh.x);
    v.y = fmaf(v.y, sc.y, sh.y);
    v.z = fmaf(v.z, sc.z, sh.z);
    v.w = fmaf(v.w, sc.w, sh.w);
    if (do_relu) {
        v.x = fmaxf(v.x, 0.f); v.y = fmaxf(v.y, 0.f);
        v.z = fmaxf(v.z, 0.f); v.w = fmaxf(v.w, 0.f);
    }
    float4 hh = h4[i];
    hh.x += v.x; hh.y += v.y; hh.z += v.z; hh.w += v.w;
    h4[i] = hh;
    ((uint2*)g_hh)[i] = f2h4(hh);
}

// ---------------- launcher ----------------
extern "C" void kernel_launch(void* const* d_in, const int* in_sizes, int n_in,
                              void* d_out, int out_size) {
    const int*   x_ids = (const int*)d_in[0];
    const int*   ei    = (const int*)d_in[1];
    const int*   eattr = (const int*)d_in[2];
    const float* atom  = (const float*)d_in[3];
    const float* bond  = (const float*)d_in[4];
    const float* W1    = (const float*)d_in[5];
    const float* b1    = (const float*)d_in[6];
    const float* g1    = (const float*)d_in[7];
    const float* bt1   = (const float*)d_in[8];
    const float* W2    = (const float*)d_in[9];
    const float* b2    = (const float*)d_in[10];
    const float* eps   = (const float*)d_in[11];
    const float* gout  = (const float*)d_in[12];
    const float* bout  = (const float*)d_in[13];
    float* h = (float*)d_out;

    cudaFuncSetAttribute(gemm_kernel<false>, cudaFuncAttributeMaxDynamicSharedMemorySize, SMEM_GEMM);
    cudaFuncSetAttribute(gemm_kernel<true>,  cudaFuncAttributeMaxDynamicSharedMemorySize, SMEM_GEMM);

    embed_kernel<<<5640, 256>>>((float4*)h, x_ids, (const float4*)atom, W1, W2);    // 0
    hist_kernel<<<EE / 256, 256>>>(ei);                                             // 1
    scan_scatter_kernel<<<40, 1024>>>(ei, eattr);                                   // 2

    for (int l = 0; l < LL; l++) {
        agg_kernel<<<NN / 8, 256>>>((const float4*)h, bond, eps, l);                // 3 (l=0)
        gemm_kernel<false><<<296, 256, SMEM_GEMM>>>(l * 2 + 0, b1 + l * DD,
                                                    nullptr, nullptr, 0);
        gemm_kernel<true><<<296, 256, SMEM_GEMM>>>(l * 2 + 1, b2 + l * DD,
                                                   g1 + l * DD, bt1 + l * DD, 1);
        residual_kernel<<<NN * 32 / 256, 256>>>((float4*)h, gout + l * DD,
                                                bout + l * DD, (l < LL - 1) ? 1 : 0);
    }
    (void)in_sizes; (void)n_in; (void)out_size;
}

// round 14
// speedup vs baseline: 1.2365x; 1.0229x over previous
#include <cuda_runtime.h>
#include <cuda_fp16.h>
#include <cuda_bf16.h>
#include <cstdint>

#define NN 40000
#define EE 640000
#define DD 128
#define LL 5
#define NTILES 625          // NN / 64 (64-row GEMM tiles, exact)

// ---------------- device scratch (static, no allocation) ----------------
__device__ float g_z0[NN * DD];   // agg output / gemm2 output
__device__ float g_y1[NN * DD];   // gemm1 output
__device__ __half g_hh[NN * DD];  // fp16 shadow of h (gather source)
__device__ int   g_rowptr[NN + 1];
__device__ int   g_cursor[NN];
__device__ int   g_packed[EE];    // (src<<5) | (attr*32)<<21, grouped by dst
__device__ int   g_bflag[40];
__device__ int   g_bpre[40];
__device__ int   g_bar;
__device__ int   g_ctr[2];        // work-stealing counters (gemm1, gemm2)
__device__ float g_sum1[DD], g_sq1[DD];   // stats of gemm1 output (BN1)
__device__ float g_sum2[DD], g_sq2[DD];   // stats of gemm2 output (BN2)
__device__ uint4 g_wth4[10 * 2048];
__device__ uint4 g_wtl4[10 * 2048];

// ---------------- helpers ----------------
__device__ __forceinline__ uint32_t smem_u32(const void* p) {
    uint32_t a;
    asm("{ .reg .u64 t; cvta.to.shared.u64 t, %1; cvt.u32.u64 %0, t; }" : "=r"(a) : "l"(p));
    return a;
}
__device__ __forceinline__ void ldsm4(uint32_t a, uint32_t& r0, uint32_t& r1,
                                      uint32_t& r2, uint32_t& r3) {
    asm volatile("ldmatrix.sync.aligned.m8n8.x4.shared.b16 {%0,%1,%2,%3}, [%4];"
                 : "=r"(r0), "=r"(r1), "=r"(r2), "=r"(r3) : "r"(a));
}
__device__ __forceinline__ void mma16816(float* c, const uint32_t* a, uint32_t b0, uint32_t b1) {
    asm volatile(
        "mma.sync.aligned.m16n8k16.row.col.f32.bf16.bf16.f32 "
        "{%0,%1,%2,%3}, {%4,%5,%6,%7}, {%8,%9}, {%0,%1,%2,%3};"
        : "+f"(c[0]), "+f"(c[1]), "+f"(c[2]), "+f"(c[3])
        : "r"(a[0]), "r"(a[1]), "r"(a[2]), "r"(a[3]), "r"(b0), "r"(b1));
}
__device__ __forceinline__ void split2(float a, float b, uint32_t& hi, uint32_t& lo) {
    __nv_bfloat16 ha = __float2bfloat16_rn(a), hb = __float2bfloat16_rn(b);
    float ra = a - __bfloat162float(ha), rb = b - __bfloat162float(hb);
    __nv_bfloat162 ph = __halves2bfloat162(ha, hb);
    __nv_bfloat162 pl = __halves2bfloat162(__float2bfloat16_rn(ra), __float2bfloat16_rn(rb));
    hi = *(uint32_t*)&ph;
    lo = *(uint32_t*)&pl;
}
__device__ __forceinline__ uint2 f2h4(float4 v) {
    __half2 lo = __floats2half2_rn(v.x, v.y);
    __half2 hi = __floats2half2_rn(v.z, v.w);
    uint2 r;
    r.x = *(unsigned*)&lo;
    r.y = *(unsigned*)&hi;
    return r;
}
// message = relu(h_src + bond) for a uint4 (8 halves)
__device__ __forceinline__ void msg4(uint4 r, uint4 e, __half2* m, __half2 z2) {
    m[0] = __hmax2(__hadd2(*(__half2*)&r.x, *(__half2*)&e.x), z2);
    m[1] = __hmax2(__hadd2(*(__half2*)&r.y, *(__half2*)&e.y), z2);
    m[2] = __hmax2(__hadd2(*(__half2*)&r.z, *(__half2*)&e.z), z2);
    m[3] = __hmax2(__hadd2(*(__half2*)&r.w, *(__half2*)&e.w), z2);
}
__device__ __forceinline__ void flushh(__half2 c0, __half2 c1, __half2 c2, __half2 c3,
                                       float2& a0, float2& a1, float2& a2, float2& a3) {
    float2 f0 = __half22float2(c0), f1 = __half22float2(c1);
    float2 f2 = __half22float2(c2), f3 = __half22float2(c3);
    a0.x += f0.x; a0.y += f0.y;
    a1.x += f1.x; a1.y += f1.y;
    a2.x += f2.x; a2.y += f2.y;
    a3.x += f3.x; a3.y += f3.y;
}

// ---------------- embed + wconv + per-replay zeroing + fp16 shadow ----------------
__global__ void embed_kernel(float4* __restrict__ h4,
                             const int* __restrict__ x_ids,
                             const float4* __restrict__ atom4,
                             const float* __restrict__ W1,
                             const float* __restrict__ W2) {
    int blk = blockIdx.x;
    if (blk < 5000) {
        int i = blk * 256 + threadIdx.x;
        if (i < NN) g_cursor[i] = 0;
        if (i < 40) { g_bflag[i] = 0; g_bpre[i] = 0; }
        if (i < 2) g_ctr[i] = 0;
        if (i == 42) g_bar = 0;
        int n = i >> 5, c = i & 31;
        float4 v = __ldg(&atom4[x_ids[n] * 32 + c]);
        h4[i] = v;
        ((uint2*)g_hh)[i] = f2h4(v);
    } else {
        int i = (blk - 5000) * 256 + threadIdx.x;   // 0..163839
        int which = i >> 14;
        int j = i & 16383;
        int n = j >> 7, k = j & 127;
        const float* W = ((which & 1) ? W2 : W1) + (which >> 1) * DD * DD;
        float v = __ldg(&W[k * DD + n]);
        __nv_bfloat16 h = __float2bfloat16_rn(v);
        float r = v - __bfloat162float(h);
        ((__nv_bfloat16*)g_wth4)[i] = h;
        ((__nv_bfloat16*)g_wtl4)[i] = __float2bfloat16_rn(r);
    }
}

// ---------------- CSR build ----------------
__global__ void hist_kernel(const int* __restrict__ ei) {
    int e = blockIdx.x * 256 + threadIdx.x;
    atomicAdd(&g_cursor[ei[EE + e]], 1);
}

__global__ void __launch_bounds__(1024) scan_scatter_kernel(const int* __restrict__ ei,
                                                            const int* __restrict__ eattr) {
    __shared__ int wsum[32];
    __shared__ int s_boff;
    int tid = threadIdx.x, lane = tid & 31, wid = tid >> 5;
    int b = blockIdx.x;
    int i = b * 1024 + tid;
    int v = (i < NN) ? g_cursor[i] : 0;
    int x = v;
    #pragma unroll
    for (int o = 1; o < 32; o <<= 1) { int t = __shfl_up_sync(~0u, x, o); if (lane >= o) x += t; }
    if (lane == 31) wsum[wid] = x;
    __syncthreads();
    if (wid == 0) {
        int y = wsum[lane];
        #pragma unroll
        for (int o = 1; o < 32; o <<= 1) { int t = __shfl_up_sync(~0u, y, o); if (lane >= o) y += t; }
        wsum[lane] = y;
    }
    __syncthreads();
    int incl = (wid ? wsum[wid - 1] : 0) + x;
    if (tid == 0) {
        int total = wsum[31];
        int p = 0;
        if (b > 0) {
            while (((volatile int*)g_bflag)[b - 1] == 0) { }
            p = ((volatile int*)g_bpre)[b - 1];
        }
        g_bpre[b] = p + total;
        __threadfence();
        ((volatile int*)g_bflag)[b] = 1;
        s_boff = p;
    }
    __syncthreads();
    int boff = s_boff;
    if (i < NN) {
        g_rowptr[i + 1] = boff + incl;
        g_cursor[i] = boff + incl - v;
    }
    if (i == 0) g_rowptr[0] = 0;
    __threadfence();
    __syncthreads();
    if (tid == 0) atomicAdd(&g_bar, 1);
    if (tid == 0) { while (((volatile int*)&g_bar)[0] < 40) { } }
    __syncthreads();
    for (int e = b * 16000 + tid; e < (b + 1) * 16000; e += 1024) {
        int d = ei[EE + e];
        int p = atomicAdd(&g_cursor[d], 1);
        g_packed[p] = (ei[e] << 5) | ((eattr[e] << 5) << 21);
    }
}

// ---------------- edge aggregation (half-warp pairing: 16B loads, 2 edges/warp-step) ----------------
__global__ void __launch_bounds__(256) agg_kernel(const float4* __restrict__ h4,
                                                  const float* __restrict__ bond_emb,
                                                  const float* __restrict__ eps, int l) {
    __shared__ uint4 sbe4[4 * 16];   // 4 bond types x 128 dims as packed half (256B each)
    int tid = threadIdx.x;
    if (blockIdx.x == 0 && tid < 128) {
        g_sum1[tid] = 0.f; g_sq1[tid] = 0.f;
        g_sum2[tid] = 0.f; g_sq2[tid] = 0.f;
        if (tid < 2) g_ctr[tid] = 0;
    }
    if (tid < 64) {
        float4 a = __ldg((const float4*)(bond_emb + l * 512) + tid * 2);
        float4 b = __ldg((const float4*)(bond_emb + l * 512) + tid * 2 + 1);
        uint2 pa = f2h4(a), pb = f2h4(b);
        sbe4[tid] = make_uint4(pa.x, pa.y, pb.x, pb.y);
    }
    __syncthreads();
    int lane = tid & 31, hf = lane >> 4, li = lane & 15;
    int v = blockIdx.x * 8 + (tid >> 5);
    float ep = 1.0f + __ldg(&eps[l]);
    const uint4* hh4 = (const uint4*)g_hh;
    const __half2 z2 = __float2half2_rn(0.f);

    // accumulators: dims li*8 .. li*8+7 (this lane's slice), per-half edge subsets
    float2 a0, a1, a2, a3;
    if (hf == 0) {
        float4 h0 = __ldg(&h4[v * 32 + li * 2]);
        float4 h1 = __ldg(&h4[v * 32 + li * 2 + 1]);
        a0 = make_float2(h0.x * ep, h0.y * ep);
        a1 = make_float2(h0.z * ep, h0.w * ep);
        a2 = make_float2(h1.x * ep, h1.y * ep);
        a3 = make_float2(h1.z * ep, h1.w * ep);
    } else {
        a0 = a1 = a2 = a3 = make_float2(0.f, 0.f);
    }

    int start = g_rowptr[v], end = g_rowptr[v + 1];
    for (int base = start; base < end; base += 32) {
        int nl = min(32, end - base);
        int pk = (base + lane < end) ? g_packed[base + lane] : 0;
        for (int j = 0; j < nl; j += 4) {
            int eA = j + hf, eB = j + 2 + hf;            // this half-warp's two edges
            int pA = __shfl_sync(~0u, pk, eA);
            int pB = __shfl_sync(~0u, pk, eB);
            bool vA = eA < nl, vB = eB < nl;
            uint4 rA = __ldg(&hh4[((pA & 0x1FFFFF) >> 1) + li]);
            uint4 eAv = sbe4[(((unsigned)pA >> 21) >> 1) + li];
            uint4 rB = __ldg(&hh4[((pB & 0x1FFFFF) >> 1) + li]);
            uint4 eBv = sbe4[(((unsigned)pB >> 21) >> 1) + li];
            __half2 mA[4], mB[4];
            msg4(rA, eAv, mA, z2);
            msg4(rB, eBv, mB, z2);
            if (vB) {
                flushh(__hadd2(mA[0], mB[0]), __hadd2(mA[1], mB[1]),
                       __hadd2(mA[2], mB[2]), __hadd2(mA[3], mB[3]), a0, a1, a2, a3);
            } else if (vA) {
                flushh(mA[0], mA[1], mA[2], mA[3], a0, a1, a2, a3);
            }
        }
    }
    // combine even/odd halves
    a0.x += __shfl_xor_sync(~0u, a0.x, 16);
    a0.y += __shfl_xor_sync(~0u, a0.y, 16);
    a1.x += __shfl_xor_sync(~0u, a1.x, 16);
    a1.y += __shfl_xor_sync(~0u, a1.y, 16);
    a2.x += __shfl_xor_sync(~0u, a2.x, 16);
    a2.y += __shfl_xor_sync(~0u, a2.y, 16);
    a3.x += __shfl_xor_sync(~0u, a3.x, 16);
    a3.y += __shfl_xor_sync(~0u, a3.y, 16);
    if (hf == 0) {
        *((float4*)g_z0 + v * 32 + li * 2)     = make_float4(a0.x, a0.y, a1.x, a1.y);
        *((float4*)g_z0 + v * 32 + li * 2 + 1) = make_float4(a2.x, a2.y, a3.x, a3.y);
    }
}

// ---------------- tensor-core GEMM (mma.sync bf16, 3-term split) ----------------
// CTA tile 64x128, 256 threads = 8 warps as 2m x 4n, warp tile m32 x n32.
// 272-byte row stride; 2 CTAs/SM at 106512 B smem.  (round-8 proven config)
#define SM_AH    0
#define SM_AL    17408
#define SM_BH    34816
#define SM_BL    69632
#define SM_SUM   104448
#define SM_SQ    104960
#define SM_SCALE 105472
#define SM_SHIFT 105984
#define SM_TILE  106496
#define SMEM_GEMM 106512

template <bool TRANS>
__global__ void __launch_bounds__(256, 2) gemm_kernel(int which,
                                                      const float* __restrict__ bias,
                                                      const float* __restrict__ gamma,
                                                      const float* __restrict__ beta,
                                                      int ctr_idx) {
    extern __shared__ char smem[];
    uint32_t sb = smem_u32(smem);
    float* s_sum   = (float*)(smem + SM_SUM);
    float* s_sq    = (float*)(smem + SM_SQ);
    float* s_scale = (float*)(smem + SM_SCALE);
    float* s_shift = (float*)(smem + SM_SHIFT);
    int*   s_tile  = (int*)(smem + SM_TILE);
    const float* A = TRANS ? g_y1 : g_z0;
    float* C       = TRANS ? g_z0 : g_y1;

    int tid = threadIdx.x, lane = tid & 31, wid = tid >> 5;
    if (tid < 128) {
        s_sum[tid] = 0.f; s_sq[tid] = 0.f;
        if (TRANS) {
            const float invN = 1.0f / (float)NN;
            float m   = g_sum1[tid] * invN;
            float var = g_sq1[tid] * invN - m * m;
            float sc  = __ldg(&gamma[tid]) * rsqrtf(var + 1e-5f);
            s_scale[tid] = sc;
            s_shift[tid] = __ldg(&beta[tid]) - m * sc;
        }
    }
    {   // stage B (hi/lo bf16, [n][k] -> padded smem), once per CTA
        const uint4* srcH = g_wth4 + which * 2048;
        const uint4* srcL = g_wtl4 + which * 2048;
        #pragma unroll
        for (int it = 0; it < 8; it++) {
            int s = it * 256 + tid;
            int row = s >> 4, ch = s & 15;
            *(uint4*)(smem + SM_BH + row * 272 + ch * 16) = __ldg(&srcH[row * 16 + ch]);
            *(uint4*)(smem + SM_BL + row * 272 + ch * 16) = __ldg(&srcL[row * 16 + ch]);
        }
    }

    int mrow = (wid & 1) * 32;
    int ncol = (wid >> 1) * 32;
    int gm = lane & 7, gh = (lane >> 3) & 1, gk = lane >> 4;
    uint32_t aA0 = sb + (mrow + gm + gh * 8) * 272 + gk * 16;
    uint32_t aB0 = sb + (ncol + gm + gh * 8) * 272 + gk * 16;
    int ar = tid >> 5, ac4 = tid & 31;

    for (;;) {
        if (tid == 0) *s_tile = atomicAdd(&g_ctr[ctr_idx], 1);
        __syncthreads();
        int t = *s_tile;
        if (t >= NTILES) break;
        int rowblk = t * 64;

        {   // stage A tile (64 rows x 128), optional BN1+relu, bf16 hi/lo split
            float4 sc, sh;
            if (TRANS) {
                sc = *(const float4*)(s_scale + ac4 * 4);
                sh = *(const float4*)(s_shift + ac4 * 4);
            }
            #pragma unroll
            for (int i = 0; i < 8; i++) {
                int rr = ar + i * 8;
                float4 v = __ldg((const float4*)(A + (rowblk + rr) * DD) + ac4);
                if (TRANS) {
                    v.x = fmaxf(fmaf(v.x, sc.x, sh.x), 0.f);
                    v.y = fmaxf(fmaf(v.y, sc.y, sh.y), 0.f);
                    v.z = fmaxf(fmaf(v.z, sc.z, sh.z), 0.f);
                    v.w = fmaxf(fmaf(v.w, sc.w, sh.w), 0.f);
                }
                uint32_t h0, l0, h1, l1;
                split2(v.x, v.y, h0, l0);
                split2(v.z, v.w, h1, l1);
                char* p = smem + rr * 272 + ac4 * 8;
                *(uint2*)(p + SM_AH) = make_uint2(h0, h1);
                *(uint2*)(p + SM_AL) = make_uint2(l0, l1);
            }
        }
        __syncthreads();

        float c[2][4][4];
        #pragma unroll
        for (int mb = 0; mb < 2; mb++)
            #pragma unroll
            for (int i = 0; i < 4; i++)
                #pragma unroll
                for (int j = 0; j < 4; j++) c[mb][i][j] = 0.f;

        #pragma unroll
        for (int ks = 0; ks < 8; ks++) {
            uint32_t off = ks * 32;
            uint32_t ah[8], al[8], bh[8], bl[8];
            ldsm4(aA0 + SM_AH + off,            ah[0], ah[1], ah[2], ah[3]);
            ldsm4(aA0 + SM_AH + 16 * 272 + off, ah[4], ah[5], ah[6], ah[7]);
            ldsm4(aA0 + SM_AL + off,            al[0], al[1], al[2], al[3]);
            ldsm4(aA0 + SM_AL + 16 * 272 + off, al[4], al[5], al[6], al[7]);
            ldsm4(aB0 + SM_BH + off,            bh[0], bh[1], bh[2], bh[3]);
            ldsm4(aB0 + SM_BH + 16 * 272 + off, bh[4], bh[5], bh[6], bh[7]);
            ldsm4(aB0 + SM_BL + off,            bl[0], bl[1], bl[2], bl[3]);
            ldsm4(aB0 + SM_BL + 16 * 272 + off, bl[4], bl[5], bl[6], bl[7]);
            #pragma unroll
            for (int mb = 0; mb < 2; mb++) {
                #pragma unroll
                for (int ng = 0; ng < 4; ng++) {
                    int bi = (ng >> 1) * 4 + (ng & 1);
                    mma16816(c[mb][ng], ah + mb * 4, bh[bi], bh[bi + 2]);
                    mma16816(c[mb][ng], al + mb * 4, bh[bi], bh[bi + 2]);
                    mma16816(c[mb][ng], ah + mb * 4, bl[bi], bl[bi + 2]);
                }
            }
        }

        // epilogue: bias, store C, column stats (shfl-reduced)
        #pragma unroll
        for (int ng = 0; ng < 4; ng++) {
            int col0 = ncol + ng * 8 + 2 * (lane & 3);
            float bx = __ldg(&bias[col0]), by = __ldg(&bias[col0 + 1]);
            float sx0 = 0.f, sq0 = 0.f, sx1 = 0.f, sq1 = 0.f;
            #pragma unroll
            for (int mb = 0; mb < 2; mb++) {
                int r0g = rowblk + mrow + mb * 16 + (lane >> 2);
                float x0 = c[mb][ng][0] + bx, x1 = c[mb][ng][1] + by;
                float x2 = c[mb][ng][2] + bx, x3 = c[mb][ng][3] + by;
                *(float2*)(C + r0g * DD + col0)       = make_float2(x0, x1);
                *(float2*)(C + (r0g + 8) * DD + col0) = make_float2(x2, x3);
                sx0 += x0 + x2; sq0 += x0 * x0 + x2 * x2;
                sx1 += x1 + x3; sq1 += x1 * x1 + x3 * x3;
            }
            #pragma unroll
            for (int d = 4; d < 32; d <<= 1) {
                sx0 += __shfl_xor_sync(~0u, sx0, d);
                sq0 += __shfl_xor_sync(~0u, sq0, d);
                sx1 += __shfl_xor_sync(~0u, sx1, d);
                sq1 += __shfl_xor_sync(~0u, sq1, d);
            }
            if ((lane >> 2) == 0) {
                atomicAdd(&s_sum[col0], sx0);
                atomicAdd(&s_sum[col0 + 1], sx1);
                atomicAdd(&s_sq[col0], sq0);
                atomicAdd(&s_sq[col0 + 1], sq1);
            }
        }
        __syncthreads();
    }
    __syncthreads();
    if (tid < 128) {
        if (TRANS) {
            atomicAdd(&g_sum2[tid], s_sum[tid]);
            atomicAdd(&g_sq2[tid],  s_sq[tid]);
        } else {
            atomicAdd(&g_sum1[tid], s_sum[tid]);
            atomicAdd(&g_sq1[tid],  s_sq[tid]);
        }
    }
}

// ---------------- BN2 + (relu) + residual + fp16 shadow refresh ----------------
__global__ void residual_kernel(float4* __restrict__ h4,
                                const float* __restrict__ gamma,
                                const float* __restrict__ beta,
                                int do_relu) {
    __shared__ float s_scale[128], s_shift[128];
    int tid = threadIdx.x;
    if (tid < 128) {
        const float invN = 1.0f / (float)NN;
        float m   = g_sum2[tid] * invN;
        float var = g_sq2[tid] * invN - m * m;
        float sc  = __ldg(&gamma[tid]) * rsqrtf(var + 1e-5f);
        s_scale[tid] = sc;
        s_shift[tid] = __ldg(&beta[tid]) - m * sc;
    }
    __syncthreads();
    int i = blockIdx.x * 256 + tid;
    int c4 = i & 31;
    float4 v  = *((const float4*)g_z0 + i);
    float4 sc = *(const float4*)(s_scale + c4 * 4);
    float4 sh = *(const float4*)(s_shift + c4 * 4);
    v.x = fmaf(v.x, sc.x, sh.x);
    v.y = fmaf(v.y, sc.y, sh.y);
    v.z = fmaf(v.z, sc.z, sh.z);
    v.w = fmaf(v.w, sc.w, sh.w);
    if (do_relu) {
        v.x = fmaxf(v.x, 0.f); v.y = fmaxf(v.y, 0.f);
        v.z = fmaxf(v.z, 0.f); v.w = fmaxf(v.w, 0.f);
    }
    float4 hh = h4[i];
    hh.x += v.x; hh.y += v.y; hh.z += v.z; hh.w += v.w;
    h4[i] = hh;
    ((uint2*)g_hh)[i] = f2h4(hh);
}

// ---------------- launcher ----------------
extern "C" void kernel_launch(void* const* d_in, const int* in_sizes, int n_in,
                              void* d_out, int out_size) {
    const int*   x_ids = (const int*)d_in[0];
    const int*   ei    = (const int*)d_in[1];
    const int*   eattr = (const int*)d_in[2];
    const float* atom  = (const float*)d_in[3];
    const float* bond  = (const float*)d_in[4];
    const float* W1    = (const float*)d_in[5];
    const float* b1    = (const float*)d_in[6];
    const float* g1    = (const float*)d_in[7];
    const float* bt1   = (const float*)d_in[8];
    const float* W2    = (const float*)d_in[9];
    const float* b2    = (const float*)d_in[10];
    const float* eps   = (const float*)d_in[11];
    const float* gout  = (const float*)d_in[12];
    const float* bout  = (const float*)d_in[13];
    float* h = (float*)d_out;

    cudaFuncSetAttribute(gemm_kernel<false>, cudaFuncAttributeMaxDynamicSharedMemorySize, SMEM_GEMM);
    cudaFuncSetAttribute(gemm_kernel<true>,  cudaFuncAttributeMaxDynamicSharedMemorySize, SMEM_GEMM);

    embed_kernel<<<5640, 256>>>((float4*)h, x_ids, (const float4*)atom, W1, W2);    // 0
    hist_kernel<<<EE / 256, 256>>>(ei);                                             // 1
    scan_scatter_kernel<<<40, 1024>>>(ei, eattr);                                   // 2

    for (int l = 0; l < LL; l++) {
        agg_kernel<<<NN / 8, 256>>>((const float4*)h, bond, eps, l);                // 3 (l=0)
        gemm_kernel<false><<<296, 256, SMEM_GEMM>>>(l * 2 + 0, b1 + l * DD,
                                                    nullptr, nullptr, 0);
        gemm_kernel<true><<<296, 256, SMEM_GEMM>>>(l * 2 + 1, b2 + l * DD,
                                                   g1 + l * DD, bt1 + l * DD, 1);
        residual_kernel<<<NN * 32 / 256, 256>>>((float4*)h, gout + l * DD,
                                                bout + l * DD, (l < LL - 1) ? 1 : 0);
    }
    (void)in_sizes; (void)n_in; (void)out_size;
}

// round 15
// speedup vs baseline: 1.2568x; 1.0165x over previous
#include <cuda_runtime.h>
#include <cuda_fp16.h>
#include <cuda_bf16.h>
#include <cstdint>

#define NN 40000
#define EE 640000
#define DD 128
#define LL 5
#define NTILES 625          // NN / 64 (64-row GEMM tiles, exact)

// ---------------- device scratch (static, no allocation) ----------------
__device__ float g_z0[NN * DD];   // agg output / gemm2 output
__device__ float g_y1[NN * DD];   // gemm1 output
__device__ __half g_hh[NN * DD];  // fp16 shadow of h (gather source)
__device__ int   g_rowptr[NN + 1];
__device__ int   g_cursor[NN];
__device__ int   g_packed[EE];    // (src<<5) | (attr*32)<<21, grouped by dst
__device__ int   g_bflag[40];
__device__ int   g_bpre[40];
__device__ int   g_bar;
__device__ int   g_ctr[2];        // work-stealing counters (gemm1, gemm2)
__device__ float g_sum1[DD], g_sq1[DD];   // stats of gemm1 output (BN1)
__device__ float g_sum2[DD], g_sq2[DD];   // stats of gemm2 output (BN2)
__device__ uint4 g_wth4[10 * 2048];
__device__ uint4 g_wtl4[10 * 2048];

// ---------------- helpers ----------------
__device__ __forceinline__ uint32_t smem_u32(const void* p) {
    uint32_t a;
    asm("{ .reg .u64 t; cvta.to.shared.u64 t, %1; cvt.u32.u64 %0, t; }" : "=r"(a) : "l"(p));
    return a;
}
__device__ __forceinline__ void ldsm4(uint32_t a, uint32_t& r0, uint32_t& r1,
                                      uint32_t& r2, uint32_t& r3) {
    asm volatile("ldmatrix.sync.aligned.m8n8.x4.shared.b16 {%0,%1,%2,%3}, [%4];"
                 : "=r"(r0), "=r"(r1), "=r"(r2), "=r"(r3) : "r"(a));
}
__device__ __forceinline__ void mma16816(float* c, const uint32_t* a, uint32_t b0, uint32_t b1) {
    asm volatile(
        "mma.sync.aligned.m16n8k16.row.col.f32.bf16.bf16.f32 "
        "{%0,%1,%2,%3}, {%4,%5,%6,%7}, {%8,%9}, {%0,%1,%2,%3};"
        : "+f"(c[0]), "+f"(c[1]), "+f"(c[2]), "+f"(c[3])
        : "r"(a[0]), "r"(a[1]), "r"(a[2]), "r"(a[3]), "r"(b0), "r"(b1));
}
__device__ __forceinline__ void split2(float a, float b, uint32_t& hi, uint32_t& lo) {
    __nv_bfloat16 ha = __float2bfloat16_rn(a), hb = __float2bfloat16_rn(b);
    float ra = a - __bfloat162float(ha), rb = b - __bfloat162float(hb);
    __nv_bfloat162 ph = __halves2bfloat162(ha, hb);
    __nv_bfloat162 pl = __halves2bfloat162(__float2bfloat16_rn(ra), __float2bfloat16_rn(rb));
    hi = *(uint32_t*)&ph;
    lo = *(uint32_t*)&pl;
}
__device__ __forceinline__ uint2 f2h4(float4 v) {
    __half2 lo = __floats2half2_rn(v.x, v.y);
    __half2 hi = __floats2half2_rn(v.z, v.w);
    uint2 r;
    r.x = *(unsigned*)&lo;
    r.y = *(unsigned*)&hi;
    return r;
}
// message = relu(h_src + bond) for a uint4 (8 halves)
__device__ __forceinline__ void msg4(uint4 r, uint4 e, __half2* m, __half2 z2) {
    m[0] = __hmax2(__hadd2(*(__half2*)&r.x, *(__half2*)&e.x), z2);
    m[1] = __hmax2(__hadd2(*(__half2*)&r.y, *(__half2*)&e.y), z2);
    m[2] = __hmax2(__hadd2(*(__half2*)&r.z, *(__half2*)&e.z), z2);
    m[3] = __hmax2(__hadd2(*(__half2*)&r.w, *(__half2*)&e.w), z2);
}
__device__ __forceinline__ void flushh(__half2 c0, __half2 c1, __half2 c2, __half2 c3,
                                       float2& a0, float2& a1, float2& a2, float2& a3) {
    float2 f0 = __half22float2(c0), f1 = __half22float2(c1);
    float2 f2 = __half22float2(c2), f3 = __half22float2(c3);
    a0.x += f0.x; a0.y += f0.y;
    a1.x += f1.x; a1.y += f1.y;
    a2.x += f2.x; a2.y += f2.y;
    a3.x += f3.x; a3.y += f3.y;
}

// ---------------- embed + wconv + per-replay zeroing + fp16 shadow ----------------
__global__ void embed_kernel(float4* __restrict__ h4,
                             const int* __restrict__ x_ids,
                             const float4* __restrict__ atom4,
                             const float* __restrict__ W1,
                             const float* __restrict__ W2) {
    int blk = blockIdx.x;
    if (blk < 5000) {
        int i = blk * 256 + threadIdx.x;
        if (i < NN) g_cursor[i] = 0;
        if (i < 40) { g_bflag[i] = 0; g_bpre[i] = 0; }
        if (i < 2) g_ctr[i] = 0;
        if (i == 42) g_bar = 0;
        int n = i >> 5, c = i & 31;
        float4 v = __ldg(&atom4[x_ids[n] * 32 + c]);
        h4[i] = v;
        ((uint2*)g_hh)[i] = f2h4(v);
    } else {
        int i = (blk - 5000) * 256 + threadIdx.x;   // 0..163839
        int which = i >> 14;
        int j = i & 16383;
        int n = j >> 7, k = j & 127;
        const float* W = ((which & 1) ? W2 : W1) + (which >> 1) * DD * DD;
        float v = __ldg(&W[k * DD + n]);
        __nv_bfloat16 h = __float2bfloat16_rn(v);
        float r = v - __bfloat162float(h);
        ((__nv_bfloat16*)g_wth4)[i] = h;
        ((__nv_bfloat16*)g_wtl4)[i] = __float2bfloat16_rn(r);
    }
}

// ---------------- CSR build: hist + scan (lookback) + scatter, one kernel ----------------
__global__ void __launch_bounds__(1024) scan_scatter_kernel(const int* __restrict__ ei,
                                                            const int* __restrict__ eattr) {
    __shared__ int wsum[32];
    __shared__ int s_boff;
    int tid = threadIdx.x, lane = tid & 31, wid = tid >> 5;
    int b = blockIdx.x;

    // phase 0: histogram (16000 edges per block)
    for (int e = b * 16000 + tid; e < (b + 1) * 16000; e += 1024)
        atomicAdd(&g_cursor[ei[EE + e]], 1);
    // grid barrier #1 (all 40 blocks resident)
    __threadfence();
    __syncthreads();
    if (tid == 0) {
        atomicAdd(&g_bar, 1);
        while (((volatile int*)&g_bar)[0] < 40) { }
    }
    __syncthreads();

    // phase 1: scan with decoupled lookback
    int i = b * 1024 + tid;
    int v = (i < NN) ? g_cursor[i] : 0;
    int x = v;
    #pragma unroll
    for (int o = 1; o < 32; o <<= 1) { int t = __shfl_up_sync(~0u, x, o); if (lane >= o) x += t; }
    if (lane == 31) wsum[wid] = x;
    __syncthreads();
    if (wid == 0) {
        int y = wsum[lane];
        #pragma unroll
        for (int o = 1; o < 32; o <<= 1) { int t = __shfl_up_sync(~0u, y, o); if (lane >= o) y += t; }
        wsum[lane] = y;
    }
    __syncthreads();
    int incl = (wid ? wsum[wid - 1] : 0) + x;
    if (tid == 0) {
        int total = wsum[31];
        int p = 0;
        if (b > 0) {
            while (((volatile int*)g_bflag)[b - 1] == 0) { }
            p = ((volatile int*)g_bpre)[b - 1];
        }
        g_bpre[b] = p + total;
        __threadfence();
        ((volatile int*)g_bflag)[b] = 1;
        s_boff = p;
    }
    __syncthreads();
    int boff = s_boff;
    if (i < NN) {
        g_rowptr[i + 1] = boff + incl;
        g_cursor[i] = boff + incl - v;   // exclusive prefix
    }
    if (i == 0) g_rowptr[0] = 0;
    // grid barrier #2
    __threadfence();
    __syncthreads();
    if (tid == 0) {
        atomicAdd(&g_bar, 1);
        while (((volatile int*)&g_bar)[0] < 80) { }
    }
    __syncthreads();

    // phase 2: scatter
    for (int e = b * 16000 + tid; e < (b + 1) * 16000; e += 1024) {
        int d = ei[EE + e];
        int p = atomicAdd(&g_cursor[d], 1);
        g_packed[p] = (ei[e] << 5) | ((eattr[e] << 5) << 21);
    }
}

// ---------------- edge aggregation (half-warp pairing: 16B loads, 2 edges/warp-step) ----------------
__global__ void __launch_bounds__(256) agg_kernel(const float4* __restrict__ h4,
                                                  const float* __restrict__ bond_emb,
                                                  const float* __restrict__ eps, int l) {
    __shared__ uint4 sbe4[4 * 16];
    int tid = threadIdx.x;
    if (blockIdx.x == 0 && tid < 128) {
        g_sum1[tid] = 0.f; g_sq1[tid] = 0.f;
        g_sum2[tid] = 0.f; g_sq2[tid] = 0.f;
        if (tid < 2) g_ctr[tid] = 0;
    }
    if (tid < 64) {
        float4 a = __ldg((const float4*)(bond_emb + l * 512) + tid * 2);
        float4 b = __ldg((const float4*)(bond_emb + l * 512) + tid * 2 + 1);
        uint2 pa = f2h4(a), pb = f2h4(b);
        sbe4[tid] = make_uint4(pa.x, pa.y, pb.x, pb.y);
    }
    __syncthreads();
    int lane = tid & 31, hf = lane >> 4, li = lane & 15;
    int v = blockIdx.x * 8 + (tid >> 5);
    float ep = 1.0f + __ldg(&eps[l]);
    const uint4* hh4 = (const uint4*)g_hh;
    const __half2 z2 = __float2half2_rn(0.f);

    float2 a0, a1, a2, a3;
    if (hf == 0) {
        float4 h0 = __ldg(&h4[v * 32 + li * 2]);
        float4 h1 = __ldg(&h4[v * 32 + li * 2 + 1]);
        a0 = make_float2(h0.x * ep, h0.y * ep);
        a1 = make_float2(h0.z * ep, h0.w * ep);
        a2 = make_float2(h1.x * ep, h1.y * ep);
        a3 = make_float2(h1.z * ep, h1.w * ep);
    } else {
        a0 = a1 = a2 = a3 = make_float2(0.f, 0.f);
    }

    int start = g_rowptr[v], end = g_rowptr[v + 1];
    for (int base = start; base < end; base += 32) {
        int nl = min(32, end - base);
        int pk = (base + lane < end) ? g_packed[base + lane] : 0;
        for (int j = 0; j < nl; j += 4) {
            int eA = j + hf, eB = j + 2 + hf;
            int pA = __shfl_sync(~0u, pk, eA);
            int pB = __shfl_sync(~0u, pk, eB);
            bool vA = eA < nl, vB = eB < nl;
            uint4 rA = __ldg(&hh4[((pA & 0x1FFFFF) >> 1) + li]);
            uint4 eAv = sbe4[(((unsigned)pA >> 21) >> 1) + li];
            uint4 rB = __ldg(&hh4[((pB & 0x1FFFFF) >> 1) + li]);
            uint4 eBv = sbe4[(((unsigned)pB >> 21) >> 1) + li];
            __half2 mA[4], mB[4];
            msg4(rA, eAv, mA, z2);
            msg4(rB, eBv, mB, z2);
            if (vB) {
                flushh(__hadd2(mA[0], mB[0]), __hadd2(mA[1], mB[1]),
                       __hadd2(mA[2], mB[2]), __hadd2(mA[3], mB[3]), a0, a1, a2, a3);
            } else if (vA) {
                flushh(mA[0], mA[1], mA[2], mA[3], a0, a1, a2, a3);
            }
        }
    }
    a0.x += __shfl_xor_sync(~0u, a0.x, 16);
    a0.y += __shfl_xor_sync(~0u, a0.y, 16);
    a1.x += __shfl_xor_sync(~0u, a1.x, 16);
    a1.y += __shfl_xor_sync(~0u, a1.y, 16);
    a2.x += __shfl_xor_sync(~0u, a2.x, 16);
    a2.y += __shfl_xor_sync(~0u, a2.y, 16);
    a3.x += __shfl_xor_sync(~0u, a3.x, 16);
    a3.y += __shfl_xor_sync(~0u, a3.y, 16);
    if (hf == 0) {
        *((float4*)g_z0 + v * 32 + li * 2)     = make_float4(a0.x, a0.y, a1.x, a1.y);
        *((float4*)g_z0 + v * 32 + li * 2 + 1) = make_float4(a2.x, a2.y, a3.x, a3.y);
    }
}

// ---------------- tensor-core GEMM (mma.sync bf16, 3-term split) ----------------
// CTA tile 64x128, 256 threads = 8 warps as 2m x 4n, warp tile m32 x n32.
// Column stats accumulated in registers across tiles, reduced once at kernel end.
#define SM_AH    0
#define SM_AL    17408
#define SM_BH    34816
#define SM_BL    69632
#define SM_SUM   104448
#define SM_SQ    104960
#define SM_SCALE 105472
#define SM_SHIFT 105984
#define SM_TILE  106496
#define SMEM_GEMM 106512

template <bool TRANS>
__global__ void __launch_bounds__(256, 2) gemm_kernel(int which,
                                                      const float* __restrict__ bias,
                                                      const float* __restrict__ gamma,
                                                      const float* __restrict__ beta,
                                                      int ctr_idx) {
    extern __shared__ char smem[];
    uint32_t sb = smem_u32(smem);
    float* s_sum   = (float*)(smem + SM_SUM);
    float* s_sq    = (float*)(smem + SM_SQ);
    float* s_scale = (float*)(smem + SM_SCALE);
    float* s_shift = (float*)(smem + SM_SHIFT);
    int*   s_tile  = (int*)(smem + SM_TILE);
    const float* A = TRANS ? g_y1 : g_z0;
    float* C       = TRANS ? g_z0 : g_y1;

    int tid = threadIdx.x, lane = tid & 31, wid = tid >> 5;
    if (tid < 128) {
        s_sum[tid] = 0.f; s_sq[tid] = 0.f;
        if (TRANS) {
            const float invN = 1.0f / (float)NN;
            float m   = g_sum1[tid] * invN;
            float var = g_sq1[tid] * invN - m * m;
            float sc  = __ldg(&gamma[tid]) * rsqrtf(var + 1e-5f);
            s_scale[tid] = sc;
            s_shift[tid] = __ldg(&beta[tid]) - m * sc;
        }
    }
    {   // stage B (hi/lo bf16, [n][k] -> padded smem), once per CTA
        const uint4* srcH = g_wth4 + which * 2048;
        const uint4* srcL = g_wtl4 + which * 2048;
        #pragma unroll
        for (int it = 0; it < 8; it++) {
            int s = it * 256 + tid;
            int row = s >> 4, ch = s & 15;
            *(uint4*)(smem + SM_BH + row * 272 + ch * 16) = __ldg(&srcH[row * 16 + ch]);
            *(uint4*)(smem + SM_BL + row * 272 + ch * 16) = __ldg(&srcL[row * 16 + ch]);
        }
    }

    int mrow = (wid & 1) * 32;
    int ncol = (wid >> 1) * 32;
    int gm = lane & 7, gh = (lane >> 3) & 1, gk = lane >> 4;
    uint32_t aA0 = sb + (mrow + gm + gh * 8) * 272 + gk * 16;
    uint32_t aB0 = sb + (ncol + gm + gh * 8) * 272 + gk * 16;
    int ar = tid >> 5, ac4 = tid & 31;

    // per-thread running column stats (columns fixed across tiles)
    float st_sx0[4] = {}, st_sx1[4] = {}, st_sq0[4] = {}, st_sq1[4] = {};

    for (;;) {
        if (tid == 0) *s_tile = atomicAdd(&g_ctr[ctr_idx], 1);
        __syncthreads();
        int t = *s_tile;
        if (t >= NTILES) break;
        int rowblk = t * 64;

        {   // stage A tile (64 rows x 128), optional BN1+relu, bf16 hi/lo split
            float4 sc, sh;
            if (TRANS) {
                sc = *(const float4*)(s_scale + ac4 * 4);
                sh = *(const float4*)(s_shift + ac4 * 4);
            }
            #pragma unroll
            for (int i = 0; i < 8; i++) {
                int rr = ar + i * 8;
                float4 v = __ldg((const float4*)(A + (rowblk + rr) * DD) + ac4);
                if (TRANS) {
                    v.x = fmaxf(fmaf(v.x, sc.x, sh.x), 0.f);
                    v.y = fmaxf(fmaf(v.y, sc.y, sh.y), 0.f);
                    v.z = fmaxf(fmaf(v.z, sc.z, sh.z), 0.f);
                    v.w = fmaxf(fmaf(v.w, sc.w, sh.w), 0.f);
                }
                uint32_t h0, l0, h1, l1;
                split2(v.x, v.y, h0, l0);
                split2(v.z, v.w, h1, l1);
                char* p = smem + rr * 272 + ac4 * 8;
                *(uint2*)(p + SM_AH) = make_uint2(h0, h1);
                *(uint2*)(p + SM_AL) = make_uint2(l0, l1);
            }
        }
        __syncthreads();

        float c[2][4][4];
        #pragma unroll
        for (int mb = 0; mb < 2; mb++)
            #pragma unroll
            for (int i = 0; i < 4; i++)
                #pragma unroll
                for (int j = 0; j < 4; j++) c[mb][i][j] = 0.f;

        #pragma unroll
        for (int ks = 0; ks < 8; ks++) {
            uint32_t off = ks * 32;
            uint32_t ah[8], al[8], bh[8], bl[8];
            ldsm4(aA0 + SM_AH + off,            ah[0], ah[1], ah[2], ah[3]);
            ldsm4(aA0 + SM_AH + 16 * 272 + off, ah[4], ah[5], ah[6], ah[7]);
            ldsm4(aA0 + SM_AL + off,            al[0], al[1], al[2], al[3]);
            ldsm4(aA0 + SM_AL + 16 * 272 + off, al[4], al[5], al[6], al[7]);
            ldsm4(aB0 + SM_BH + off,            bh[0], bh[1], bh[2], bh[3]);
            ldsm4(aB0 + SM_BH + 16 * 272 + off, bh[4], bh[5], bh[6], bh[7]);
            ldsm4(aB0 + SM_BL + off,            bl[0], bl[1], bl[2], bl[3]);
            ldsm4(aB0 + SM_BL + 16 * 272 + off, bl[4], bl[5], bl[6], bl[7]);
            #pragma unroll
            for (int mb = 0; mb < 2; mb++) {
                #pragma unroll
                for (int ng = 0; ng < 4; ng++) {
                    int bi = (ng >> 1) * 4 + (ng & 1);
                    mma16816(c[mb][ng], ah + mb * 4, bh[bi], bh[bi + 2]);
                    mma16816(c[mb][ng], al + mb * 4, bh[bi], bh[bi + 2]);
                    mma16816(c[mb][ng], ah + mb * 4, bl[bi], bl[bi + 2]);
                }
            }
        }

        // epilogue: bias, store C; stats into registers only
        #pragma unroll
        for (int ng = 0; ng < 4; ng++) {
            int col0 = ncol + ng * 8 + 2 * (lane & 3);
            float bx = __ldg(&bias[col0]), by = __ldg(&bias[col0 + 1]);
            #pragma unroll
            for (int mb = 0; mb < 2; mb++) {
                int r0g = rowblk + mrow + mb * 16 + (lane >> 2);
                float x0 = c[mb][ng][0] + bx, x1 = c[mb][ng][1] + by;
                float x2 = c[mb][ng][2] + bx, x3 = c[mb][ng][3] + by;
                *(float2*)(C + r0g * DD + col0)       = make_float2(x0, x1);
                *(float2*)(C + (r0g + 8) * DD + col0) = make_float2(x2, x3);
                st_sx0[ng] += x0 + x2; st_sq0[ng] += x0 * x0 + x2 * x2;
                st_sx1[ng] += x1 + x3; st_sq1[ng] += x1 * x1 + x3 * x3;
            }
        }
        __syncthreads();
    }

    // final stats reduction (once per kernel)
    #pragma unroll
    for (int ng = 0; ng < 4; ng++) {
        float sx0 = st_sx0[ng], sq0 = st_sq0[ng], sx1 = st_sx1[ng], sq1 = st_sq1[ng];
        #pragma unroll
        for (int d = 4; d < 32; d <<= 1) {
            sx0 += __shfl_xor_sync(~0u, sx0, d);
            sq0 += __shfl_xor_sync(~0u, sq0, d);
            sx1 += __shfl_xor_sync(~0u, sx1, d);
            sq1 += __shfl_xor_sync(~0u, sq1, d);
        }
        if ((lane >> 2) == 0) {
            int col0 = ncol + ng * 8 + 2 * (lane & 3);
            atomicAdd(&s_sum[col0], sx0);
            atomicAdd(&s_sum[col0 + 1], sx1);
            atomicAdd(&s_sq[col0], sq0);
            atomicAdd(&s_sq[col0 + 1], sq1);
        }
    }
    __syncthreads();
    if (tid < 128) {
        if (TRANS) {
            atomicAdd(&g_sum2[tid], s_sum[tid]);
            atomicAdd(&g_sq2[tid],  s_sq[tid]);
        } else {
            atomicAdd(&g_sum1[tid], s_sum[tid]);
            atomicAdd(&g_sq1[tid],  s_sq[tid]);
        }
    }
}

// ---------------- BN2 + (relu) + residual + fp16 shadow refresh ----------------
__global__ void residual_kernel(float4* __restrict__ h4,
                                const float* __restrict__ gamma,
                                const float* __restrict__ beta,
                                int do_relu) {
    __shared__ float s_scale[128], s_shift[128];
    int tid = threadIdx.x;
    if (tid < 128) {
        const float invN = 1.0f / (float)NN;
        float m   = g_sum2[tid] * invN;
        float var = g_sq2[tid] * invN - m * m;
        float sc  = __ldg(&gamma[tid]) * rsqrtf(var + 1e-5f);
        s_scale[tid] = sc;
        s_shift[tid] = __ldg(&beta[tid]) - m * sc;
    }
    __syncthreads();
    int i = blockIdx.x * 256 + tid;
    int c4 = i & 31;
    float4 v  = *((const float4*)g_z0 + i);
    float4 sc = *(const float4*)(s_scale + c4 * 4);
    float4 sh = *(const float4*)(s_shift + c4 * 4);
    v.x = fmaf(v.x, sc.x, sh.x);
    v.y = fmaf(v.y, sc.y, sh.y);
    v.z = fmaf(v.z, sc.z, sh.z);
    v.w = fmaf(v.w, sc.w, sh.w);
    if (do_relu) {
        v.x = fmaxf(v.x, 0.f); v.y = fmaxf(v.y, 0.f);
        v.z = fmaxf(v.z, 0.f); v.w = fmaxf(v.w, 0.f);
    }
    float4 hh = h4[i];
    hh.x += v.x; hh.y += v.y; hh.z += v.z; hh.w += v.w;
    h4[i] = hh;
    ((uint2*)g_hh)[i] = f2h4(hh);
}

// ---------------- launcher ----------------
extern "C" void kernel_launch(void* const* d_in, const int* in_sizes, int n_in,
                              void* d_out, int out_size) {
    const int*   x_ids = (const int*)d_in[0];
    const int*   ei    = (const int*)d_in[1];
    const int*   eattr = (const int*)d_in[2];
    const float* atom  = (const float*)d_in[3];
    const float* bond  = (const float*)d_in[4];
    const float* W1    = (const float*)d_in[5];
    const float* b1    = (const float*)d_in[6];
    const float* g1    = (const float*)d_in[7];
    const float* bt1   = (const float*)d_in[8];
    const float* W2    = (const float*)d_in[9];
    const float* b2    = (const float*)d_in[10];
    const float* eps   = (const float*)d_in[11];
    const float* gout  = (const float*)d_in[12];
    const float* bout  = (const float*)d_in[13];
    float* h = (float*)d_out;

    cudaFuncSetAttribute(gemm_kernel<false>, cudaFuncAttributeMaxDynamicSharedMemorySize, SMEM_GEMM);
    cudaFuncSetAttribute(gemm_kernel<true>,  cudaFuncAttributeMaxDynamicSharedMemorySize, SMEM_GEMM);

    embed_kernel<<<5640, 256>>>((float4*)h, x_ids, (const float4*)atom, W1, W2);    // 0
    scan_scatter_kernel<<<40, 1024>>>(ei, eattr);                                   // 1

    for (int l = 0; l < LL; l++) {
        agg_kernel<<<NN / 8, 256>>>((const float4*)h, bond, eps, l);                // 2 (l=0)
        gemm_kernel<false><<<296, 256, SMEM_GEMM>>>(l * 2 + 0, b1 + l * DD,
                                                    nullptr, nullptr, 0);           // 3 (l=0) <- profiled
        gemm_kernel<true><<<296, 256, SMEM_GEMM>>>(l * 2 + 1, b2 + l * DD,
                                                   g1 + l * DD, bt1 + l * DD, 1);
        residual_kernel<<<NN * 32 / 256, 256>>>((float4*)h, gout + l * DD,
                                                bout + l * DD, (l < LL - 1) ? 1 : 0);
    }
    (void)in_sizes; (void)n_in; (void)out_size;
}